// round 8
// baseline (speedup 1.0000x reference)
#include <cuda_runtime.h>
#include <cuda_bf16.h>
#include <cstdint>

#define RTYPES 8
#define CSZ 128
#define MCAP 10000
#define ECAP 100000
#define PCAP (ECAP + (RTYPES + 1) * CSZ)

// ---------------- device scratch (no runtime alloc allowed) ----------------
__device__ float g_num[MCAP*128];
__device__ float g_denom[MCAP*8];
__device__ int   g_perm[PCAP];
__device__ int   g_counts[RTYPES];
__device__ int   g_cursor[RTYPES];
// Pre-swizzled bf16 hi/lo weight images (K-major blocked atoms + xor swizzle)
__device__ __align__(128) unsigned char g_Bq[RTYPES*2*32768];
__device__ __align__(128) unsigned char g_Bk[RTYPES*2*49152];
__device__ __align__(128) unsigned char g_Bv[RTYPES*2*49152];

// ---------------- SMEM byte layout for k_edge ----------------
#define OFF_AD_HI 0          // 32768 (later: Bk/Bv lo stage, then bounce)
#define OFF_AD_LO 32768
#define OFF_AS_HI 65536      // 49152
#define OFF_AS_LO 114688
#define OFF_B     163840     // 49152 B stage
#define OFF_EX    212992     // float[128*8]
#define OFF_DST   217088     // int[128]
#define SMEM_EDGE 217664

typedef unsigned char uchar;

__device__ __forceinline__ float warp_sum(float v) {
#pragma unroll
  for (int o = 16; o; o >>= 1) v += __shfl_xor_sync(0xffffffffu, v, o);
  return v;
}

// blocked-atom K-major byte offset: atom = 8 rows x 64 bf16 (1024B),
// 16 m-atoms, k-atoms stride 16KB; xor swizzle for conflict-free ldsm.
__host__ __device__ __forceinline__ uint32_t koff(int m, int k) {
  uint32_t off = (uint32_t)(((m >> 3) + (k >> 6) * 16) * 1024 + (m & 7) * 128 + (k & 63) * 2);
  return off ^ ((off >> 3) & 0x70);
}
__device__ __forceinline__ uint32_t koff2(uint32_t rowbase, int k) {
  uint32_t off = rowbase + ((k >> 6) << 14) + ((k & 63) << 1);
  return off ^ ((off >> 3) & 0x70);
}

__device__ __forceinline__ void cp16(uint32_t dst, const void* src) {
  asm volatile("cp.async.cg.shared.global [%0], [%1], 16;" :: "r"(dst), "l"(src));
}
#define CP_COMMIT() asm volatile("cp.async.commit_group;")
#define CP_WAIT0()  asm volatile("cp.async.wait_group 0;")

__device__ __forceinline__ void ldsm4(uint32_t* r, uint32_t a) {
  asm volatile("ldmatrix.sync.aligned.m8n8.x4.shared.b16 {%0,%1,%2,%3}, [%4];"
    : "=r"(r[0]), "=r"(r[1]), "=r"(r[2]), "=r"(r[3]) : "r"(a));
}
__device__ __forceinline__ void mma16816(float* c, const uint32_t* a, const uint32_t* b) {
  asm volatile("mma.sync.aligned.m16n8k16.row.col.f32.bf16.bf16.f32 "
    "{%0,%1,%2,%3}, {%4,%5,%6,%7}, {%8,%9}, {%0,%1,%2,%3};"
    : "+f"(c[0]), "+f"(c[1]), "+f"(c[2]), "+f"(c[3])
    : "r"(a[0]), "r"(a[1]), "r"(a[2]), "r"(a[3]), "r"(b[0]), "r"(b[1]));
}
__device__ __forceinline__ void red4(float* p, float4 v) {
  asm volatile("red.global.add.v4.f32 [%0], {%1,%2,%3,%4};"
    :: "l"(p), "f"(v.x), "f"(v.y), "f"(v.z), "f"(v.w) : "memory");
}

// One pass: C[32 x NT*16] += A[32xK] @ B[.xK]^T for one warp tile (m0, nb0).
template<int NK, int NT>
__device__ __forceinline__ void gemm_pass(
    uint32_t aB, uint32_t bB, int m0, int nb0, int lane,
    float (&acc)[2][2*NT][4])
{
  const int r0 = m0 + (lane & 15);
  const int r1 = r0 + 16;
  const uint32_t arb0 = (uint32_t)(((r0 >> 3) << 10) + ((r0 & 7) << 7));
  const uint32_t arb1 = (uint32_t)(((r1 >> 3) << 10) + ((r1 & 7) << 7));
  const int ak = (lane >> 4) << 3;
  const int bn = nb0 + (lane & 7) + ((lane >> 4) << 3);
  const int bk = ((lane >> 3) & 1) << 3;
  uint32_t brb[NT];
#pragma unroll
  for (int p = 0; p < NT; ++p) {
    int n = bn + p * 16;
    brb[p] = (uint32_t)(((n >> 3) << 10) + ((n & 7) << 7));
  }
#pragma unroll
  for (int ks = 0; ks < NK; ++ks) {
    const int k0 = ks << 4;
    uint32_t A0[4], A1[4], B[NT][4];
    ldsm4(A0, aB + koff2(arb0, k0 + ak));
    ldsm4(A1, aB + koff2(arb1, k0 + ak));
#pragma unroll
    for (int p = 0; p < NT; ++p) ldsm4(B[p], bB + koff2(brb[p], k0 + bk));
#pragma unroll
    for (int p = 0; p < NT; ++p) {
      mma16816(acc[0][2*p],   A0, &B[p][0]);
      mma16816(acc[0][2*p+1], A0, &B[p][2]);
      mma16816(acc[1][2*p],   A1, &B[p][0]);
      mma16816(acc[1][2*p+1], A1, &B[p][2]);
    }
  }
}

// ================= fused init + count + weight-image prep =================
__global__ void __launch_bounds__(256) k_prep(
    const int* __restrict__ etype, int E, int M,
    const float* __restrict__ Wq, const float* __restrict__ Wk,
    const float* __restrict__ Wv, int NBI)
{
  __shared__ int loc[RTYPES];
  const int bid = blockIdx.x, tid = threadIdx.x;
  if (bid < NBI) {
    int i = bid * 256 + tid;
    if (i < M*128) g_num[i] = 0.f;
    if (i < M*8)   g_denom[i] = 0.f;
    if (i < PCAP)  g_perm[i] = -1;
    if (i < RTYPES) { g_counts[i] = 0; g_cursor[i] = 0; }
    return;
  }
  if (bid < NBI + 128) {
    if (tid < RTYPES) loc[tid] = 0;
    __syncthreads();
    for (int i = (bid - NBI)*256 + tid; i < E; i += 128*256)
      atomicAdd(&loc[etype[i]], 1);
    __syncthreads();
    if (tid < RTYPES && loc[tid]) atomicAdd(&g_counts[tid], loc[tid]);
    return;
  }
  int idx = (bid - NBI - 128) * 256 + tid;
  float val; uchar* hbase; uint32_t off; int half_stride;
  if (idx < 131072) {
    int r = idx >> 14, rem = idx & 16383, k = rem >> 7, n = rem & 127;
    val = Wq[r*16384 + k*128 + n];
    hbase = g_Bq + r*65536; half_stride = 32768; off = koff(n, k);
  } else if (idx < 131072 + 196608) {
    int i2 = idx - 131072;
    int r = i2 / 24576, rem = i2 % 24576, k = rem >> 7, n = rem & 127;
    val = (k < 160) ? Wk[r*20480 + k*128 + n] : 0.f;
    hbase = g_Bk + r*98304; half_stride = 49152; off = koff(n, k);
  } else {
    int i3 = idx - 131072 - 196608;
    if (i3 >= 196608) return;
    int r = i3 / 24576, rem = i3 % 24576, k = rem >> 7, n = rem & 127;
    val = (k < 160) ? Wv[r*20480 + k*128 + n] : 0.f;
    hbase = g_Bv + r*98304; half_stride = 49152; off = koff(n, k);
  }
  __nv_bfloat16 hi = __float2bfloat16(val);
  __nv_bfloat16 lo = __float2bfloat16(val - __bfloat162float(hi));
  *(__nv_bfloat16*)(hbase + off) = hi;
  *(__nv_bfloat16*)(hbase + half_stride + off) = lo;
}

// ================= scatter (with inline prefix scan) =================
__global__ void k_scatter(const int* __restrict__ etype, int E) {
  __shared__ int loc[RTYPES], base[RTYPES], pf[RTYPES];
  const int t = threadIdx.x;
  if (t < RTYPES) loc[t] = 0;
  __syncthreads();
  const int start = blockIdx.x * 1024;
  const int end = min(start + 1024, E);
  for (int i = start + t; i < end; i += 256) atomicAdd(&loc[etype[i]], 1);
  if (t == 0) {
    int b = 0;
    for (int r = 0; r < RTYPES; ++r) {
      pf[r] = b;
      b += ((g_counts[r] + CSZ - 1) / CSZ) * CSZ;
    }
  }
  __syncthreads();
  if (t < RTYPES) {
    base[t] = pf[t] + (loc[t] ? atomicAdd(&g_cursor[t], loc[t]) : 0);
    loc[t] = 0;
  }
  __syncthreads();
  for (int i = start + t; i < end; i += 256) {
    int r = etype[i];
    g_perm[base[r] + atomicAdd(&loc[r], 1)] = i;
  }
}

// ================= main edge kernel: in-SMEM LN + warp-MMA 3-pass =========
__global__ void __launch_bounds__(512, 1) k_edge(
    const float* __restrict__ src_h, const float* __restrict__ src_tw,
    const float* __restrict__ src_tb, const float* __restrict__ edge_h,
    const float* __restrict__ date, const int* __restrict__ src_idx,
    const int* __restrict__ dst_idx, const int* __restrict__ etype,
    const float* __restrict__ sg, const float* __restrict__ sb,
    const float* __restrict__ dg, const float* __restrict__ db)
{
  extern __shared__ __align__(1024) char sm[];
  float* sEx  = (float*)(sm + OFF_EX);
  int*   sDst = (int*)(sm + OFF_DST);
  const uint32_t smb = (uint32_t)__cvta_generic_to_shared(sm);

  const int tid = threadIdx.x, wid = tid >> 5, lane = tid & 31;
  const int chunk = blockIdx.x;

  const int e0 = g_perm[chunk * CSZ];
  if (e0 < 0) return;           // pure-padding chunk
  const int et = etype[e0];

  // prefetch Bq_hi during Phase A
  { const uchar* bq = g_Bq + et*65536;
    for (int o = tid*16; o < 32768; o += 8192) cp16(smb + OFF_B + o, bq + o); }
  CP_COMMIT();

  if (tid < CSZ) {
    int e = g_perm[chunk*CSZ + tid];
    sDst[tid] = (e >= 0) ? dst_idx[e] : -1;
  }
  __syncthreads();

  // ---------------- Phase A: dia + LayerNorm -> bf16 hi/lo into SMEM ------
  for (int c = wid; c < CSZ; c += 16) {
    const int e = g_perm[chunk*CSZ + c];
    if (e < 0) continue;   // pad row: stale data is row-local, guarded at scatter
    const float t = date[e];
    const int s = src_idx[e];
    const int d = sDst[c];

    float xd[4];
#pragma unroll
    for (int kk = 0; kk < 4; ++kk) xd[kk] = src_h[d*128 + lane + 32*kk];
    xd[0] *= __sinf(src_tw[d*32+lane]*t + src_tb[d*32+lane]);
    float mu = warp_sum(xd[0]+xd[1]+xd[2]+xd[3]) * (1.f/128.f);
    float vv = 0.f;
#pragma unroll
    for (int kk = 0; kk < 4; ++kk) { float dl = xd[kk]-mu; vv = fmaf(dl,dl,vv); }
    float rs = rsqrtf(warp_sum(vv)*(1.f/128.f) + 1e-5f);
#pragma unroll
    for (int kk = 0; kk < 4; ++kk) {
      int i = lane + 32*kk;
      float v = (xd[kk]-mu)*rs*dg[i] + db[i];
      __nv_bfloat16 hi = __float2bfloat16(v);
      __nv_bfloat16 lo = __float2bfloat16(v - __bfloat162float(hi));
      uint32_t o = koff(c, i);
      *(__nv_bfloat16*)(sm + OFF_AD_HI + o) = hi;
      *(__nv_bfloat16*)(sm + OFF_AD_LO + o) = lo;
    }

    float xs[5];
#pragma unroll
    for (int kk = 0; kk < 4; ++kk) xs[kk] = src_h[s*128 + lane + 32*kk];
    xs[0] *= __sinf(src_tw[s*32+lane]*t + src_tb[s*32+lane]);
    xs[4] = edge_h[e*32 + lane];
    mu = warp_sum(xs[0]+xs[1]+xs[2]+xs[3]+xs[4]) * (1.f/160.f);
    vv = 0.f;
#pragma unroll
    for (int kk = 0; kk < 5; ++kk) { float dl = xs[kk]-mu; vv = fmaf(dl,dl,vv); }
    rs = rsqrtf(warp_sum(vv)*(1.f/160.f) + 1e-5f);
#pragma unroll
    for (int kk = 0; kk < 5; ++kk) {
      int i = lane + 32*kk;
      float v = (xs[kk]-mu)*rs*sg[i] + sb[i];
      __nv_bfloat16 hi = __float2bfloat16(v);
      __nv_bfloat16 lo = __float2bfloat16(v - __bfloat162float(hi));
      uint32_t o = koff(c, i);
      *(__nv_bfloat16*)(sm + OFF_AS_HI + o) = hi;
      *(__nv_bfloat16*)(sm + OFF_AS_LO + o) = lo;
    }
    {  // K-pad [160,192): zero both halves
      uint32_t o = koff(c, 160 + lane);
      *(unsigned short*)(sm + OFF_AS_HI + o) = 0;
      *(unsigned short*)(sm + OFF_AS_LO + o) = 0;
    }
  }
  CP_WAIT0();
  __syncthreads();

  const int m0 = (wid >> 2) * 32;
  const int n0 = (wid & 3) * 32;
  const uint32_t aDhi = smb + OFF_AD_HI, aDlo = smb + OFF_AD_LO;
  const uint32_t aShi = smb + OFF_AS_HI, aSlo = smb + OFF_AS_LO;
  const uint32_t bS = smb + OFF_B, bA = smb;   // bA = A_d region reused for B-lo

  // ---- q GEMM: passes 1-2 (Bq_hi), restage Bq_lo, pass 3 ----
  float accQ[2][4][4];
#pragma unroll
  for (int a = 0; a < 2; ++a)
#pragma unroll
    for (int b = 0; b < 4; ++b)
#pragma unroll
      for (int cc = 0; cc < 4; ++cc) accQ[a][b][cc] = 0.f;
  gemm_pass<8,2>(aDhi, bS, m0, n0, lane, accQ);
  gemm_pass<8,2>(aDlo, bS, m0, n0, lane, accQ);
  __syncthreads();
  { const uchar* bq = g_Bq + et*65536 + 32768;
    for (int o = tid*16; o < 32768; o += 8192) cp16(smb + OFF_B + o, bq + o); }
  CP_COMMIT(); CP_WAIT0(); __syncthreads();
  gemm_pass<8,2>(aDhi, bS, m0, n0, lane, accQ);
  __syncthreads();

  // ---- stage Bk hi->B, lo->A_d region (single wait) ----
  { const uchar* bk = g_Bk + et*98304;
    for (int o = tid*16; o < 49152; o += 8192) cp16(smb + OFF_B + o, bk + o);
    for (int o = tid*16; o < 49152; o += 8192) cp16(smb + o, bk + 49152 + o); }
  CP_COMMIT(); CP_WAIT0(); __syncthreads();

  // ---- k GEMM in two 16-col halves with incremental per-head dots ----
  const float scl = 0.0883883476483184f;  // 1/sqrt(128)
#pragma unroll
  for (int h = 0; h < 2; ++h) {
    float accC[2][2][4];
#pragma unroll
    for (int a = 0; a < 2; ++a)
#pragma unroll
      for (int b = 0; b < 2; ++b)
#pragma unroll
        for (int cc = 0; cc < 4; ++cc) accC[a][b][cc] = 0.f;
    gemm_pass<10,1>(aShi, bS, m0, n0 + h*16, lane, accC);
    gemm_pass<10,1>(aSlo, bS, m0, n0 + h*16, lane, accC);
    gemm_pass<10,1>(aShi, bA, m0, n0 + h*16, lane, accC);
    const int head = (n0 >> 4) + h;
#pragma unroll
    for (int mi = 0; mi < 2; ++mi)
#pragma unroll
      for (int rh = 0; rh < 2; ++rh) {
        float p = 0.f;
#pragma unroll
        for (int nj = 0; nj < 2; ++nj) {
          p = fmaf(accQ[mi][2*h+nj][2*rh],   accC[mi][nj][2*rh],   p);
          p = fmaf(accQ[mi][2*h+nj][2*rh+1], accC[mi][nj][2*rh+1], p);
        }
        p += __shfl_xor_sync(0xffffffffu, p, 1);
        p += __shfl_xor_sync(0xffffffffu, p, 2);
        if ((lane & 3) == 0) {
          int row = m0 + mi*16 + rh*8 + (lane >> 2);
          float ex = __expf(p * scl);
          sEx[row*8 + head] = ex;
          int d = sDst[row];
          if (d >= 0) atomicAdd(&g_denom[d*8 + head], ex);
        }
      }
  }
  __syncthreads();

  // ---- stage Bv hi->B, lo->A_d (single wait) ----
  { const uchar* bv = g_Bv + et*98304;
    for (int o = tid*16; o < 49152; o += 8192) cp16(smb + OFF_B + o, bv + o);
    for (int o = tid*16; o < 49152; o += 8192) cp16(smb + o, bv + 49152 + o); }
  CP_COMMIT(); CP_WAIT0(); __syncthreads();

  // ---- v GEMM (3 passes, full 32-col tile) ----
  float accV[2][4][4];
#pragma unroll
  for (int a = 0; a < 2; ++a)
#pragma unroll
    for (int b = 0; b < 4; ++b)
#pragma unroll
      for (int cc = 0; cc < 4; ++cc) accV[a][b][cc] = 0.f;
  gemm_pass<10,2>(aShi, bS, m0, n0, lane, accV);
  gemm_pass<10,2>(aSlo, bS, m0, n0, lane, accV);
  gemm_pass<10,2>(aShi, bA, m0, n0, lane, accV);
  __syncthreads();   // all reads of A_d region done -> reuse as bounce

  // ---- epilogue: scale by ex -> xor-swizzled bounce -> red.v4 scatter ----
  {
    float* bounce = (float*)sm;   // 128x128 fp32, physical col = col ^ ((row&7)<<2)
#pragma unroll
    for (int mi = 0; mi < 2; ++mi)
#pragma unroll
      for (int nj = 0; nj < 4; ++nj) {
        int col = n0 + nj*8 + (lane & 3)*2;
        int head = (n0 >> 4) + (nj >> 1);
        int row0 = m0 + mi*16 + (lane >> 2);
        int row1 = row0 + 8;
        float ex0 = sEx[row0*8 + head], ex1 = sEx[row1*8 + head];
        *(float2*)&bounce[row0*128 + (col ^ ((row0 & 7) << 2))] =
            make_float2(accV[mi][nj][0]*ex0, accV[mi][nj][1]*ex0);
        *(float2*)&bounce[row1*128 + (col ^ ((row1 & 7) << 2))] =
            make_float2(accV[mi][nj][2]*ex1, accV[mi][nj][3]*ex1);
      }
  }
  __syncthreads();
  {
    const float* bounce = (const float*)sm;
#pragma unroll
    for (int i = 0; i < 8; ++i) {
      int e = wid*8 + i;
      int d = sDst[e];
      if (d < 0) continue;
      int col = (lane*4) ^ ((e & 7) << 2);
      float4 v = *(const float4*)&bounce[e*128 + col];
      red4(&g_num[d*128 + (lane*4)], v);
    }
  }
}

// ================= output kernel =================
__global__ void __launch_bounds__(128) k_out(
    const float* __restrict__ src_h, const int* __restrict__ ntype,
    const float* __restrict__ Wa, const float* __restrict__ h_bias,
    const float* __restrict__ skip, float* __restrict__ out, int M)
{
  extern __shared__ float smem[];
  float* sWa = smem;
  float* sh  = smem + 16384;
  const int tt  = blockIdx.y;
  const int tid = threadIdx.x;
  {
    const float4* srcw = (const float4*)(Wa + tt*16384);
    for (int idx = tid; idx < 4096; idx += 128) ((float4*)sWa)[idx] = srcw[idx];
  }
  const float gate = 1.f / (1.f + __expf(-skip[tt]));
  const float bias = h_bias[tt*128 + tid];
  __syncthreads();

  const int m1 = min((int)(blockIdx.x + 1) * 64, M);
  for (int m = blockIdx.x * 64; m < m1; ++m) {
    if (ntype[m] != tt) continue;
    float dden = g_denom[m*8 + (tid >> 4)];
    float hv = (dden > 0.f) ? g_num[m*128 + tid] / dden : 0.f;
    sh[tid] = hv + bias;
    __syncthreads();
    float a0 = 0.f, a1 = 0.f, a2 = 0.f, a3 = 0.f;
#pragma unroll
    for (int i = 0; i < 128; i += 4) {
      a0 = fmaf(sh[i+0], sWa[(i+0)*128 + tid], a0);
      a1 = fmaf(sh[i+1], sWa[(i+1)*128 + tid], a1);
      a2 = fmaf(sh[i+2], sWa[(i+2)*128 + tid], a2);
      a3 = fmaf(sh[i+3], sWa[(i+3)*128 + tid], a3);
    }
    out[m*128 + tid] = ((a0+a1)+(a2+a3))*gate + src_h[m*128 + tid]*(1.f - gate);
    __syncthreads();
  }
}

extern "C" void kernel_launch(void* const* d_in, const int* in_sizes, int n_in,
                              void* d_out, int out_size) {
  const float* src_h  = (const float*)d_in[0];
  const float* src_tw = (const float*)d_in[1];
  const float* src_tb = (const float*)d_in[2];
  const float* edge_h = (const float*)d_in[3];
  const float* date   = (const float*)d_in[4];
  const int*   src_idx= (const int*)d_in[5];
  const int*   dst_idx= (const int*)d_in[6];
  const int*   etype  = (const int*)d_in[7];
  const int*   ntype  = (const int*)d_in[8];
  const float* Wq     = (const float*)d_in[9];
  const float* Wk     = (const float*)d_in[10];
  const float* Wv     = (const float*)d_in[11];
  const float* Wa     = (const float*)d_in[12];
  const float* h_bias = (const float*)d_in[13];
  const float* skip   = (const float*)d_in[14];
  const float* sg     = (const float*)d_in[15];
  const float* sb     = (const float*)d_in[16];
  const float* dg     = (const float*)d_in[17];
  const float* db     = (const float*)d_in[18];
  float* out = (float*)d_out;

  const int E = in_sizes[4];
  const int M = in_sizes[8];
  const int T = in_sizes[14];
  const int NB = (E + CSZ - 1)/CSZ + RTYPES;

  cudaFuncSetAttribute(k_edge, cudaFuncAttributeMaxDynamicSharedMemorySize, SMEM_EDGE);
  cudaFuncSetAttribute(k_out, cudaFuncAttributeMaxDynamicSharedMemorySize, (16384+128)*4);

  int initN = M * 128; if (PCAP > initN) initN = PCAP;
  const int NBI = (initN + 255) / 256;
  const int NBP = (131072 + 196608 + 196608 + 255) / 256;
  k_prep<<<NBI + 128 + NBP, 256>>>(etype, E, M, Wq, Wk, Wv, NBI);
  k_scatter<<<(E + 1023)/1024, 256>>>(etype, E);
  k_edge<<<NB, 512, SMEM_EDGE>>>(src_h, src_tw, src_tb, edge_h, date,
                                 src_idx, dst_idx, etype, sg, sb, dg, db);
  dim3 g3((M + 63)/64, T);
  k_out<<<g3, 128, (16384+128)*4>>>(src_h, ntype, Wa, h_bias, skip, out, M);
}

// round 9
// speedup vs baseline: 1.1813x; 1.1813x over previous
#include <cuda_runtime.h>
#include <cuda_bf16.h>
#include <cstdint>

#define RTYPES 8
#define TTYPES 4
#define CSZ 128
#define MCAP 10000
#define ECAP 100000
#define PCAP (ECAP + (RTYPES + 1) * CSZ)
#define NPCAP (MCAP + TTYPES*64)

// ---------------- device scratch (no runtime alloc allowed) ----------------
__device__ float g_num[MCAP*128];
__device__ float g_denom[MCAP*8];
__device__ int   g_perm[PCAP];
__device__ int   g_counts[RTYPES];
__device__ int   g_cursor[RTYPES];
__device__ int   g_nperm[NPCAP];
__device__ int   g_ncounts[TTYPES];
__device__ int   g_ncursor[TTYPES];
// Pre-swizzled bf16 hi/lo weight images (K-major blocked atoms + xor swizzle)
__device__ __align__(128) unsigned char g_Bq[RTYPES*2*32768];
__device__ __align__(128) unsigned char g_Bk[RTYPES*2*49152];
__device__ __align__(128) unsigned char g_Bv[RTYPES*2*49152];

// ---------------- SMEM byte layout for k_edge ----------------
#define OFF_AD_HI 0          // 32768 (later: Bk/Bv lo stage, then bounce)
#define OFF_AD_LO 32768
#define OFF_AS_HI 65536      // 49152
#define OFF_AS_LO 114688
#define OFF_B     163840     // 49152 B stage
#define OFF_EX    212992     // float[128*8]
#define OFF_DST   217088     // int[128]
#define SMEM_EDGE 217664

typedef unsigned char uchar;

// blocked-atom K-major byte offset: atom = 8 rows x 64 bf16 (1024B),
// 16 m-atoms, k-atoms stride 16KB; xor swizzle for conflict-free ldsm.
__host__ __device__ __forceinline__ uint32_t koff(int m, int k) {
  uint32_t off = (uint32_t)(((m >> 3) + (k >> 6) * 16) * 1024 + (m & 7) * 128 + (k & 63) * 2);
  return off ^ ((off >> 3) & 0x70);
}
__device__ __forceinline__ uint32_t koff2(uint32_t rowbase, int k) {
  uint32_t off = rowbase + ((k >> 6) << 14) + ((k & 63) << 1);
  return off ^ ((off >> 3) & 0x70);
}

__device__ __forceinline__ void cp16(uint32_t dst, const void* src) {
  asm volatile("cp.async.cg.shared.global [%0], [%1], 16;" :: "r"(dst), "l"(src));
}
#define CP_COMMIT() asm volatile("cp.async.commit_group;")
#define CP_WAIT0()  asm volatile("cp.async.wait_group 0;")

__device__ __forceinline__ void ldsm4(uint32_t* r, uint32_t a) {
  asm volatile("ldmatrix.sync.aligned.m8n8.x4.shared.b16 {%0,%1,%2,%3}, [%4];"
    : "=r"(r[0]), "=r"(r[1]), "=r"(r[2]), "=r"(r[3]) : "r"(a));
}
__device__ __forceinline__ void mma16816(float* c, const uint32_t* a, const uint32_t* b) {
  asm volatile("mma.sync.aligned.m16n8k16.row.col.f32.bf16.bf16.f32 "
    "{%0,%1,%2,%3}, {%4,%5,%6,%7}, {%8,%9}, {%0,%1,%2,%3};"
    : "+f"(c[0]), "+f"(c[1]), "+f"(c[2]), "+f"(c[3])
    : "r"(a[0]), "r"(a[1]), "r"(a[2]), "r"(a[3]), "r"(b[0]), "r"(b[1]));
}
__device__ __forceinline__ void red4(float* p, float4 v) {
  asm volatile("red.global.add.v4.f32 [%0], {%1,%2,%3,%4};"
    :: "l"(p), "f"(v.x), "f"(v.y), "f"(v.z), "f"(v.w) : "memory");
}
__device__ __forceinline__ unsigned short bfbits(float v) {
  __nv_bfloat16 b = __float2bfloat16(v);
  return *(unsigned short*)&b;
}

// One pass: C[32 x NT*16] += A[32xK] @ B[.xK]^T for one warp tile (m0, nb0).
template<int NK, int NT>
__device__ __forceinline__ void gemm_pass(
    uint32_t aB, uint32_t bB, int m0, int nb0, int lane,
    float (&acc)[2][2*NT][4])
{
  const int r0 = m0 + (lane & 15);
  const int r1 = r0 + 16;
  const uint32_t arb0 = (uint32_t)(((r0 >> 3) << 10) + ((r0 & 7) << 7));
  const uint32_t arb1 = (uint32_t)(((r1 >> 3) << 10) + ((r1 & 7) << 7));
  const int ak = (lane >> 4) << 3;
  const int bn = nb0 + (lane & 7) + ((lane >> 4) << 3);
  const int bk = ((lane >> 3) & 1) << 3;
  uint32_t brb[NT];
#pragma unroll
  for (int p = 0; p < NT; ++p) {
    int n = bn + p * 16;
    brb[p] = (uint32_t)(((n >> 3) << 10) + ((n & 7) << 7));
  }
#pragma unroll
  for (int ks = 0; ks < NK; ++ks) {
    const int k0 = ks << 4;
    uint32_t A0[4], A1[4], B[NT][4];
    ldsm4(A0, aB + koff2(arb0, k0 + ak));
    ldsm4(A1, aB + koff2(arb1, k0 + ak));
#pragma unroll
    for (int p = 0; p < NT; ++p) ldsm4(B[p], bB + koff2(brb[p], k0 + bk));
#pragma unroll
    for (int p = 0; p < NT; ++p) {
      mma16816(acc[0][2*p],   A0, &B[p][0]);
      mma16816(acc[0][2*p+1], A0, &B[p][2]);
      mma16816(acc[1][2*p],   A1, &B[p][0]);
      mma16816(acc[1][2*p+1], A1, &B[p][2]);
    }
  }
}

// ====== fused init + edge-count + node-count + weight-image prep ==========
__global__ void __launch_bounds__(256) k_prep(
    const int* __restrict__ etype, const int* __restrict__ ntype, int E, int M,
    const float* __restrict__ Wq, const float* __restrict__ Wk,
    const float* __restrict__ Wv, int NBI)
{
  __shared__ int loc[RTYPES];
  const int bid = blockIdx.x, tid = threadIdx.x;
  if (bid < NBI) {
    int i = bid * 256 + tid;
    if (i < M*128) g_num[i] = 0.f;
    if (i < M*8)   g_denom[i] = 0.f;
    if (i < PCAP)  g_perm[i] = -1;
    if (i < NPCAP) g_nperm[i] = -1;
    if (i < RTYPES) { g_counts[i] = 0; g_cursor[i] = 0; }
    if (i < TTYPES) { g_ncounts[i] = 0; g_ncursor[i] = 0; }
    return;
  }
  if (bid < NBI + 128) {   // edge-type histogram
    if (tid < RTYPES) loc[tid] = 0;
    __syncthreads();
    for (int i = (bid - NBI)*256 + tid; i < E; i += 128*256)
      atomicAdd(&loc[etype[i]], 1);
    __syncthreads();
    if (tid < RTYPES && loc[tid]) atomicAdd(&g_counts[tid], loc[tid]);
    return;
  }
  if (bid < NBI + 144) {   // node-type histogram
    if (tid < TTYPES) loc[tid] = 0;
    __syncthreads();
    for (int i = (bid - NBI - 128)*256 + tid; i < M; i += 16*256)
      atomicAdd(&loc[ntype[i]], 1);
    __syncthreads();
    if (tid < TTYPES && loc[tid]) atomicAdd(&g_ncounts[tid], loc[tid]);
    return;
  }
  // weight prep: one task = (r, n, 4 consecutive k) -> 8B hi + 8B lo stores
  int idx = (bid - NBI - 144) * 256 + tid;
  const float* W; uchar* hbase; int r, n, k0, Kdim, half_stride, wstride;
  if (idx < 32768) {           // Wq: 8r x 128n x 32kg
    r = idx >> 12; int rem = idx & 4095; int kg = rem >> 7; n = rem & 127;
    k0 = kg*4; W = Wq + r*16384; hbase = g_Bq + r*65536;
    Kdim = 128; half_stride = 32768; wstride = 128;
  } else if (idx < 32768 + 49152) {  // Wk: 8r x 128n x 48kg
    int i2 = idx - 32768;
    r = i2 / 6144; int rem = i2 % 6144; int kg = rem >> 7; n = rem & 127;
    k0 = kg*4; W = Wk + r*20480; hbase = g_Bk + r*98304;
    Kdim = 160; half_stride = 49152; wstride = 128;
  } else if (idx < 32768 + 2*49152) { // Wv
    int i3 = idx - 32768 - 49152;
    r = i3 / 6144; int rem = i3 % 6144; int kg = rem >> 7; n = rem & 127;
    k0 = kg*4; W = Wv + r*20480; hbase = g_Bv + r*98304;
    Kdim = 160; half_stride = 49152; wstride = 128;
  } else return;
  unsigned short h[4], l[4];
#pragma unroll
  for (int i = 0; i < 4; ++i) {
    int k = k0 + i;
    float val = (k < Kdim) ? W[k*wstride + n] : 0.f;
    __nv_bfloat16 hi = __float2bfloat16(val);
    float lof = val - __bfloat162float(hi);
    h[i] = *(unsigned short*)&hi;
    l[i] = bfbits(lof);
  }
  uint32_t off = koff(n, k0);   // 8B-aligned, swizzle-uniform run
  *(uint2*)(hbase + off) = make_uint2((uint32_t)h[0] | ((uint32_t)h[1]<<16),
                                      (uint32_t)h[2] | ((uint32_t)h[3]<<16));
  *(uint2*)(hbase + half_stride + off) = make_uint2((uint32_t)l[0] | ((uint32_t)l[1]<<16),
                                                    (uint32_t)l[2] | ((uint32_t)l[3]<<16));
}

// ================= edge scatter (with inline prefix scan) =================
__global__ void k_scatter(const int* __restrict__ etype, int E) {
  __shared__ int loc[RTYPES], base[RTYPES], pf[RTYPES];
  const int t = threadIdx.x;
  if (t < RTYPES) loc[t] = 0;
  __syncthreads();
  const int start = blockIdx.x * 1024;
  const int end = min(start + 1024, E);
  for (int i = start + t; i < end; i += 256) atomicAdd(&loc[etype[i]], 1);
  if (t == 0) {
    int b = 0;
    for (int r = 0; r < RTYPES; ++r) {
      pf[r] = b;
      b += ((g_counts[r] + CSZ - 1) / CSZ) * CSZ;
    }
  }
  __syncthreads();
  if (t < RTYPES) {
    base[t] = pf[t] + (loc[t] ? atomicAdd(&g_cursor[t], loc[t]) : 0);
    loc[t] = 0;
  }
  __syncthreads();
  for (int i = start + t; i < end; i += 256) {
    int r = etype[i];
    g_perm[base[r] + atomicAdd(&loc[r], 1)] = i;
  }
}

// ================= node scatter (64-aligned type-pure buckets) ============
__global__ void k_nscatter(const int* __restrict__ ntype, int M) {
  __shared__ int loc[TTYPES], base[TTYPES], pf[TTYPES];
  const int t = threadIdx.x;
  if (t < TTYPES) loc[t] = 0;
  __syncthreads();
  const int start = blockIdx.x * 1024;
  const int end = min(start + 1024, M);
  for (int i = start + t; i < end; i += 256) atomicAdd(&loc[ntype[i]], 1);
  if (t == 0) {
    int b = 0;
    for (int r = 0; r < TTYPES; ++r) {
      pf[r] = b;
      b += ((g_ncounts[r] + 63) / 64) * 64;
    }
  }
  __syncthreads();
  if (t < TTYPES) {
    base[t] = pf[t] + (loc[t] ? atomicAdd(&g_ncursor[t], loc[t]) : 0);
    loc[t] = 0;
  }
  __syncthreads();
  for (int i = start + t; i < end; i += 256) {
    int r = ntype[i];
    g_nperm[base[r] + atomicAdd(&loc[r], 1)] = i;
  }
}

// ======== main edge kernel: pipelined in-SMEM LN + warp-MMA 3-pass ========
__global__ void __launch_bounds__(512, 1) k_edge(
    const float* __restrict__ src_h, const float* __restrict__ src_tw,
    const float* __restrict__ src_tb, const float* __restrict__ edge_h,
    const float* __restrict__ date, const int* __restrict__ src_idx,
    const int* __restrict__ dst_idx, const int* __restrict__ etype,
    const float* __restrict__ sg, const float* __restrict__ sb,
    const float* __restrict__ dg, const float* __restrict__ db)
{
  extern __shared__ __align__(1024) char sm[];
  float* sEx  = (float*)(sm + OFF_EX);
  int*   sDst = (int*)(sm + OFF_DST);
  const uint32_t smb = (uint32_t)__cvta_generic_to_shared(sm);

  const int tid = threadIdx.x, wid = tid >> 5, lane = tid & 31;
  const int chunk = blockIdx.x;
  const int cbase = chunk * CSZ;

  const int e0 = g_perm[cbase];
  if (e0 < 0) return;           // pure-padding chunk
  const int et = etype[e0];

  // prefetch Bq_hi during Phase A
  { const uchar* bq = g_Bq + et*65536;
    for (int o = tid*16; o < 32768; o += 8192) cp16(smb + OFF_B + o, bq + o); }
  CP_COMMIT();

  if (tid < CSZ) {
    int e = g_perm[cbase + tid];
    sDst[tid] = (e >= 0) ? dst_idx[e] : -1;
  }
  __syncthreads();

  // ------- Phase A: software-pipelined gather + LN -> bf16 hi/lo SMEM -----
  {
    int eN = g_perm[cbase + wid];
    float tN=0.f, xdN0=0,xdN1=0,xdN2=0,xdN3=0, twdN=0, tbdN=0;
    float xsN0=0,xsN1=0,xsN2=0,xsN3=0, twsN=0, tbsN=0, ehN=0;
    if (eN >= 0) {
      tN = date[eN];
      int s = src_idx[eN], d = sDst[wid];
      xdN0 = src_h[d*128+lane];    xdN1 = src_h[d*128+lane+32];
      xdN2 = src_h[d*128+lane+64]; xdN3 = src_h[d*128+lane+96];
      twdN = src_tw[d*32+lane];    tbdN = src_tb[d*32+lane];
      xsN0 = src_h[s*128+lane];    xsN1 = src_h[s*128+lane+32];
      xsN2 = src_h[s*128+lane+64]; xsN3 = src_h[s*128+lane+96];
      twsN = src_tw[s*32+lane];    tbsN = src_tb[s*32+lane];
      ehN  = edge_h[eN*32+lane];
    }
#pragma unroll
    for (int j = 0; j < 8; ++j) {
      const int c = wid + 16*j;
      const int e = eN;
      float t = tN;
      float xd0=xdN0, xd1=xdN1, xd2=xdN2, xd3=xdN3, twd=twdN, tbd=tbdN;
      float xs0=xsN0, xs1=xsN1, xs2=xsN2, xs3=xsN3, tws=twsN, tbs=tbsN, eh=ehN;
      if (j < 7) {                      // issue next row's loads now (MLP)
        const int cN = wid + 16*(j+1);
        eN = g_perm[cbase + cN];
        if (eN >= 0) {
          tN = date[eN];
          int s = src_idx[eN], d = sDst[cN];
          xdN0 = src_h[d*128+lane];    xdN1 = src_h[d*128+lane+32];
          xdN2 = src_h[d*128+lane+64]; xdN3 = src_h[d*128+lane+96];
          twdN = src_tw[d*32+lane];    tbdN = src_tb[d*32+lane];
          xsN0 = src_h[s*128+lane];    xsN1 = src_h[s*128+lane+32];
          xsN2 = src_h[s*128+lane+64]; xsN3 = src_h[s*128+lane+96];
          twsN = src_tw[s*32+lane];    tbsN = src_tb[s*32+lane];
          ehN  = edge_h[eN*32+lane];
        }
      }
      if (e < 0) continue;   // pad row: stale SMEM is row-local, guarded later

      // dst LN (fused moments: var = E[x^2] - mu^2)
      xd0 *= __sinf(twd*t + tbd);
      {
        float s1 = ((xd0+xd1)+(xd2+xd3));
        float s2 = fmaf(xd0,xd0, fmaf(xd1,xd1, fmaf(xd2,xd2, xd3*xd3)));
#pragma unroll
        for (int o = 16; o; o >>= 1) {
          s1 += __shfl_xor_sync(0xffffffffu, s1, o);
          s2 += __shfl_xor_sync(0xffffffffu, s2, o);
        }
        float mu = s1 * (1.f/128.f);
        float rs = rsqrtf(fmaf(-mu, mu, s2*(1.f/128.f)) + 1e-5f);
        float vout[4] = {xd0, xd1, xd2, xd3};
#pragma unroll
        for (int kk = 0; kk < 4; ++kk) {
          int i = lane + 32*kk;
          float v = (vout[kk]-mu)*rs*dg[i] + db[i];
          __nv_bfloat16 hi = __float2bfloat16(v);
          uint32_t o2 = koff(c, i);
          *(__nv_bfloat16*)(sm + OFF_AD_HI + o2) = hi;
          *(unsigned short*)(sm + OFF_AD_LO + o2) = bfbits(v - __bfloat162float(hi));
        }
      }
      // src LN (160 dims)
      xs0 *= __sinf(tws*t + tbs);
      {
        float s1 = (((xs0+xs1)+(xs2+xs3))+eh);
        float s2 = fmaf(xs0,xs0, fmaf(xs1,xs1, fmaf(xs2,xs2, fmaf(xs3,xs3, eh*eh))));
#pragma unroll
        for (int o = 16; o; o >>= 1) {
          s1 += __shfl_xor_sync(0xffffffffu, s1, o);
          s2 += __shfl_xor_sync(0xffffffffu, s2, o);
        }
        float mu = s1 * (1.f/160.f);
        float rs = rsqrtf(fmaf(-mu, mu, s2*(1.f/160.f)) + 1e-5f);
        float vout[5] = {xs0, xs1, xs2, xs3, eh};
#pragma unroll
        for (int kk = 0; kk < 5; ++kk) {
          int i = lane + 32*kk;
          float v = (vout[kk]-mu)*rs*sg[i] + sb[i];
          __nv_bfloat16 hi = __float2bfloat16(v);
          uint32_t o2 = koff(c, i);
          *(__nv_bfloat16*)(sm + OFF_AS_HI + o2) = hi;
          *(unsigned short*)(sm + OFF_AS_LO + o2) = bfbits(v - __bfloat162float(hi));
        }
        uint32_t o2 = koff(c, 160 + lane);   // K-pad [160,192)
        *(unsigned short*)(sm + OFF_AS_HI + o2) = 0;
        *(unsigned short*)(sm + OFF_AS_LO + o2) = 0;
      }
    }
  }
  CP_WAIT0();
  __syncthreads();

  const int m0 = (wid >> 2) * 32;
  const int n0 = (wid & 3) * 32;
  const uint32_t aDhi = smb + OFF_AD_HI, aDlo = smb + OFF_AD_LO;
  const uint32_t aShi = smb + OFF_AS_HI, aSlo = smb + OFF_AS_LO;
  const uint32_t bS = smb + OFF_B, bA = smb;   // bA = A_d region reused for B-lo

  // ---- q GEMM: passes 1-2 (Bq_hi), restage Bq_lo, pass 3 ----
  float accQ[2][4][4];
#pragma unroll
  for (int a = 0; a < 2; ++a)
#pragma unroll
    for (int b = 0; b < 4; ++b)
#pragma unroll
      for (int cc = 0; cc < 4; ++cc) accQ[a][b][cc] = 0.f;
  gemm_pass<8,2>(aDhi, bS, m0, n0, lane, accQ);
  gemm_pass<8,2>(aDlo, bS, m0, n0, lane, accQ);
  __syncthreads();
  { const uchar* bq = g_Bq + et*65536 + 32768;
    for (int o = tid*16; o < 32768; o += 8192) cp16(smb + OFF_B + o, bq + o); }
  CP_COMMIT(); CP_WAIT0(); __syncthreads();
  gemm_pass<8,2>(aDhi, bS, m0, n0, lane, accQ);
  __syncthreads();

  // ---- stage Bk hi->B, lo->A_d region (single wait) ----
  { const uchar* bk = g_Bk + et*98304;
    for (int o = tid*16; o < 49152; o += 8192) cp16(smb + OFF_B + o, bk + o);
    for (int o = tid*16; o < 49152; o += 8192) cp16(smb + o, bk + 49152 + o); }
  CP_COMMIT(); CP_WAIT0(); __syncthreads();

  // ---- k GEMM in two 16-col halves with incremental per-head dots ----
  const float scl = 0.0883883476483184f;  // 1/sqrt(128)
#pragma unroll
  for (int h = 0; h < 2; ++h) {
    float accC[2][2][4];
#pragma unroll
    for (int a = 0; a < 2; ++a)
#pragma unroll
      for (int b = 0; b < 2; ++b)
#pragma unroll
        for (int cc = 0; cc < 4; ++cc) accC[a][b][cc] = 0.f;
    gemm_pass<10,1>(aShi, bS, m0, n0 + h*16, lane, accC);
    gemm_pass<10,1>(aSlo, bS, m0, n0 + h*16, lane, accC);
    gemm_pass<10,1>(aShi, bA, m0, n0 + h*16, lane, accC);
    const int head = (n0 >> 4) + h;
#pragma unroll
    for (int mi = 0; mi < 2; ++mi)
#pragma unroll
      for (int rh = 0; rh < 2; ++rh) {
        float p = 0.f;
#pragma unroll
        for (int nj = 0; nj < 2; ++nj) {
          p = fmaf(accQ[mi][2*h+nj][2*rh],   accC[mi][nj][2*rh],   p);
          p = fmaf(accQ[mi][2*h+nj][2*rh+1], accC[mi][nj][2*rh+1], p);
        }
        p += __shfl_xor_sync(0xffffffffu, p, 1);
        p += __shfl_xor_sync(0xffffffffu, p, 2);
        if ((lane & 3) == 0) {
          int row = m0 + mi*16 + rh*8 + (lane >> 2);
          float ex = __expf(p * scl);
          sEx[row*8 + head] = ex;
          int d = sDst[row];
          if (d >= 0) atomicAdd(&g_denom[d*8 + head], ex);
        }
      }
  }
  __syncthreads();

  // ---- stage Bv hi->B, lo->A_d (single wait) ----
  { const uchar* bv = g_Bv + et*98304;
    for (int o = tid*16; o < 49152; o += 8192) cp16(smb + OFF_B + o, bv + o);
    for (int o = tid*16; o < 49152; o += 8192) cp16(smb + o, bv + 49152 + o); }
  CP_COMMIT(); CP_WAIT0(); __syncthreads();

  // ---- v GEMM (3 passes, full 32-col tile) ----
  float accV[2][4][4];
#pragma unroll
  for (int a = 0; a < 2; ++a)
#pragma unroll
    for (int b = 0; b < 4; ++b)
#pragma unroll
      for (int cc = 0; cc < 4; ++cc) accV[a][b][cc] = 0.f;
  gemm_pass<10,2>(aShi, bS, m0, n0, lane, accV);
  gemm_pass<10,2>(aSlo, bS, m0, n0, lane, accV);
  gemm_pass<10,2>(aShi, bA, m0, n0, lane, accV);
  __syncthreads();   // all reads of A_d region done -> reuse as bounce

  // ---- epilogue: scale by ex -> xor-swizzled bounce -> red.v4 scatter ----
  {
    float* bounce = (float*)sm;   // 128x128 fp32, physical col = col ^ ((row&7)<<2)
#pragma unroll
    for (int mi = 0; mi < 2; ++mi)
#pragma unroll
      for (int nj = 0; nj < 4; ++nj) {
        int col = n0 + nj*8 + (lane & 3)*2;
        int head = (n0 >> 4) + (nj >> 1);
        int row0 = m0 + mi*16 + (lane >> 2);
        int row1 = row0 + 8;
        float ex0 = sEx[row0*8 + head], ex1 = sEx[row1*8 + head];
        *(float2*)&bounce[row0*128 + (col ^ ((row0 & 7) << 2))] =
            make_float2(accV[mi][nj][0]*ex0, accV[mi][nj][1]*ex0);
        *(float2*)&bounce[row1*128 + (col ^ ((row1 & 7) << 2))] =
            make_float2(accV[mi][nj][2]*ex1, accV[mi][nj][3]*ex1);
      }
  }
  __syncthreads();
  {
    const float* bounce = (const float*)sm;
#pragma unroll
    for (int i = 0; i < 8; ++i) {
      int e = wid*8 + i;
      int d = sDst[e];
      if (d < 0) continue;
      int col = (lane*4) ^ ((e & 7) << 2);
      float4 v = *(const float4*)&bounce[e*128 + col];
      red4(&g_num[d*128 + (lane*4)], v);
    }
  }
}

// ====== output kernel: type-pure 64-node chunks, 2 nodes in flight ========
__global__ void __launch_bounds__(256) k_out(
    const float* __restrict__ src_h, const int* __restrict__ ntype,
    const float* __restrict__ Wa, const float* __restrict__ h_bias,
    const float* __restrict__ skip, float* __restrict__ out)
{
  extern __shared__ float smem[];
  float* sWa = smem;              // 128x128
  float* sh  = smem + 16384;      // 2x128
  const int tid = threadIdx.x, col = tid & 127, half = tid >> 7;
  const int m0 = g_nperm[blockIdx.x * 64];
  if (m0 < 0) return;             // pad-only chunk
  const int tt = ntype[m0];
  {
    const uchar* w = (const uchar*)(Wa + tt*16384);
    uint32_t dst = (uint32_t)__cvta_generic_to_shared(sWa);
    for (int o = tid*16; o < 65536; o += 4096) cp16(dst + o, w + o);
    CP_COMMIT();
  }
  const float gate = 1.f / (1.f + __expf(-skip[tt]));
  const float bias = h_bias[tt*128 + col];
  CP_WAIT0();
  __syncthreads();

  for (int it = 0; it < 32; ++it) {
    const int m = g_nperm[blockIdx.x*64 + it*2 + half];
    if (m >= 0) {
      float dden = g_denom[m*8 + (col >> 4)];
      float hv = (dden > 0.f) ? g_num[m*128 + col] / dden : 0.f;
      sh[half*128 + col] = hv + bias;
    }
    __syncthreads();
    float a0 = 0.f, a1 = 0.f, a2 = 0.f, a3 = 0.f;
    const float* shh = sh + half*128;
#pragma unroll
    for (int i = 0; i < 128; i += 4) {
      a0 = fmaf(shh[i+0], sWa[(i+0)*128 + col], a0);
      a1 = fmaf(shh[i+1], sWa[(i+1)*128 + col], a1);
      a2 = fmaf(shh[i+2], sWa[(i+2)*128 + col], a2);
      a3 = fmaf(shh[i+3], sWa[(i+3)*128 + col], a3);
    }
    if (m >= 0)
      out[m*128 + col] = ((a0+a1)+(a2+a3))*gate + src_h[m*128 + col]*(1.f - gate);
    __syncthreads();
  }
}

extern "C" void kernel_launch(void* const* d_in, const int* in_sizes, int n_in,
                              void* d_out, int out_size) {
  const float* src_h  = (const float*)d_in[0];
  const float* src_tw = (const float*)d_in[1];
  const float* src_tb = (const float*)d_in[2];
  const float* edge_h = (const float*)d_in[3];
  const float* date   = (const float*)d_in[4];
  const int*   src_idx= (const int*)d_in[5];
  const int*   dst_idx= (const int*)d_in[6];
  const int*   etype  = (const int*)d_in[7];
  const int*   ntype  = (const int*)d_in[8];
  const float* Wq     = (const float*)d_in[9];
  const float* Wk     = (const float*)d_in[10];
  const float* Wv     = (const float*)d_in[11];
  const float* Wa     = (const float*)d_in[12];
  const float* h_bias = (const float*)d_in[13];
  const float* skip   = (const float*)d_in[14];
  const float* sg     = (const float*)d_in[15];
  const float* sb     = (const float*)d_in[16];
  const float* dg     = (const float*)d_in[17];
  const float* db     = (const float*)d_in[18];
  float* out = (float*)d_out;

  const int E = in_sizes[4];
  const int M = in_sizes[8];
  const int NB = (E + CSZ - 1)/CSZ + RTYPES;
  const int NNB = (M + 63)/64 + TTYPES;

  cudaFuncSetAttribute(k_edge, cudaFuncAttributeMaxDynamicSharedMemorySize, SMEM_EDGE);
  cudaFuncSetAttribute(k_out, cudaFuncAttributeMaxDynamicSharedMemorySize, (16384+256)*4);

  int initN = M * 128; if (PCAP > initN) initN = PCAP;
  const int NBI = (initN + 255) / 256;
  const int NBP = (32768 + 2*49152 + 255) / 256;   // 512
  k_prep<<<NBI + 144 + NBP, 256>>>(etype, ntype, E, M, Wq, Wk, Wv, NBI);
  k_scatter<<<(E + 1023)/1024, 256>>>(etype, E);
  k_nscatter<<<(M + 1023)/1024, 256>>>(ntype, M);
  k_edge<<<NB, 512, SMEM_EDGE>>>(src_h, src_tw, src_tb, edge_h, date,
                                 src_idx, dst_idx, etype, sg, sb, dg, db);
  k_out<<<NNB, 256, (16384+256)*4>>>(src_h, ntype, Wa, h_bias, skip, out);
}

// round 12
// speedup vs baseline: 1.1946x; 1.0113x over previous
#include <cuda_runtime.h>
#include <cuda_fp16.h>
#include <cstdint>

#define RTYPES 8
#define TTYPES 4
#define CSZ 128
#define MCAP 10000
#define ECAP 100000
#define PCAP (ECAP + (RTYPES + 1) * CSZ)
#define NPCAP (MCAP + TTYPES*64)

// ---------------- device scratch (no runtime alloc allowed) ----------------
__device__ float g_num[MCAP*128];
__device__ float g_denom[MCAP*8];
__device__ int   g_perm[PCAP];
__device__ int   g_counts[RTYPES];
__device__ int   g_cursor[RTYPES];
__device__ int   g_nperm[NPCAP];
__device__ int   g_ncounts[TTYPES];
__device__ int   g_ncursor[TTYPES];
// Pre-swizzled fp16 weight images (hi only; K-major blocked atoms + xor swizzle)
__device__ __align__(128) unsigned char g_Bq[RTYPES*32768];
__device__ __align__(128) unsigned char g_Bk[RTYPES*49152];
__device__ __align__(128) unsigned char g_Bv[RTYPES*49152];

// ---------------- SMEM byte layout for k_edge (231936 total) ----------------
#define OFF_AD    0          // 32768  A_d fp16 (hi only; q is 1-pass)
#define OFF_AS_HI 32768      // 49152
#define OFF_AS_LO 81920      // 49152
#define OFF_B1    131072     // 49152  (Bq_hi 32K, later Bv_hi 48K)
#define OFF_B2    180224     // 49152  (Bk_hi)
#define OFF_EX    229376     // half[128*8] = 2048
#define OFF_DST   231424     // int[128]   = 512
#define SMEM_EDGE 231936
// bounce (128x128 fp32 = 64KB) overlays OFF_AS_HI after v GEMM

typedef unsigned char uchar;

// blocked-atom K-major byte offset: atom = 8 rows x 64 fp16 (1024B),
// 16 m-atoms, k-atoms stride 16KB; xor swizzle for conflict-free ldsm.
__host__ __device__ __forceinline__ uint32_t koff(int m, int k) {
  uint32_t off = (uint32_t)(((m >> 3) + (k >> 6) * 16) * 1024 + (m & 7) * 128 + (k & 63) * 2);
  return off ^ ((off >> 3) & 0x70);
}
__device__ __forceinline__ uint32_t koff2(uint32_t rowbase, int k) {
  uint32_t off = rowbase + ((k >> 6) << 14) + ((k & 63) << 1);
  return off ^ ((off >> 3) & 0x70);
}

__device__ __forceinline__ void cp16(uint32_t dst, const void* src) {
  asm volatile("cp.async.cg.shared.global [%0], [%1], 16;" :: "r"(dst), "l"(src));
}
#define CP_COMMIT() asm volatile("cp.async.commit_group;")
#define CP_WAIT0()  asm volatile("cp.async.wait_group 0;")
#define CP_WAIT1()  asm volatile("cp.async.wait_group 1;")

__device__ __forceinline__ void ldsm4(uint32_t* r, uint32_t a) {
  asm volatile("ldmatrix.sync.aligned.m8n8.x4.shared.b16 {%0,%1,%2,%3}, [%4];"
    : "=r"(r[0]), "=r"(r[1]), "=r"(r[2]), "=r"(r[3]) : "r"(a));
}
__device__ __forceinline__ void mma16816(float* c, const uint32_t* a, const uint32_t* b) {
  asm volatile("mma.sync.aligned.m16n8k16.row.col.f32.f16.f16.f32 "
    "{%0,%1,%2,%3}, {%4,%5,%6,%7}, {%8,%9}, {%0,%1,%2,%3};"
    : "+f"(c[0]), "+f"(c[1]), "+f"(c[2]), "+f"(c[3])
    : "r"(a[0]), "r"(a[1]), "r"(a[2]), "r"(a[3]), "r"(b[0]), "r"(b[1]));
}
__device__ __forceinline__ void red4(float* p, float4 v) {
  asm volatile("red.global.add.v4.f32 [%0], {%1,%2,%3,%4};"
    :: "l"(p), "f"(v.x), "f"(v.y), "f"(v.z), "f"(v.w) : "memory");
}
__device__ __forceinline__ unsigned short hbits(float v) {
  __half h = __float2half_rn(v);
  return *(unsigned short*)&h;
}

// One pass: C[32 x NT*16] += A[32xK] @ B[.xK]^T for one warp tile (m0, nb0).
template<int NK, int NT>
__device__ __forceinline__ void gemm_pass(
    uint32_t aB, uint32_t bB, int m0, int nb0, int lane,
    float (&acc)[2][2*NT][4])
{
  const int r0 = m0 + (lane & 15);
  const int r1 = r0 + 16;
  const uint32_t arb0 = (uint32_t)(((r0 >> 3) << 10) + ((r0 & 7) << 7));
  const uint32_t arb1 = (uint32_t)(((r1 >> 3) << 10) + ((r1 & 7) << 7));
  const int ak = (lane >> 4) << 3;
  const int bn = nb0 + (lane & 7) + ((lane >> 4) << 3);
  const int bk = ((lane >> 3) & 1) << 3;
  uint32_t brb[NT];
#pragma unroll
  for (int p = 0; p < NT; ++p) {
    int n = bn + p * 16;
    brb[p] = (uint32_t)(((n >> 3) << 10) + ((n & 7) << 7));
  }
#pragma unroll
  for (int ks = 0; ks < NK; ++ks) {
    const int k0 = ks << 4;
    uint32_t A0[4], A1[4], B[NT][4];
    ldsm4(A0, aB + koff2(arb0, k0 + ak));
    ldsm4(A1, aB + koff2(arb1, k0 + ak));
#pragma unroll
    for (int p = 0; p < NT; ++p) ldsm4(B[p], bB + koff2(brb[p], k0 + bk));
#pragma unroll
    for (int p = 0; p < NT; ++p) {
      mma16816(acc[0][2*p],   A0, &B[p][0]);
      mma16816(acc[0][2*p+1], A0, &B[p][2]);
      mma16816(acc[1][2*p],   A1, &B[p][0]);
      mma16816(acc[1][2*p+1], A1, &B[p][2]);
    }
  }
}

// ====== fused init + edge-count + node-count + weight-image prep ==========
__global__ void __launch_bounds__(256) k_prep(
    const int* __restrict__ etype, const int* __restrict__ ntype, int E, int M,
    const float* __restrict__ Wq, const float* __restrict__ Wk,
    const float* __restrict__ Wv, int NBI)
{
  __shared__ int loc[RTYPES];
  const int bid = blockIdx.x, tid = threadIdx.x;
  if (bid < NBI) {   // vectorized init
    int i = bid * 256 + tid;
    const int z0 = M*32, z1 = z0 + M*2, z2 = z1 + PCAP/4, z3 = z2 + NPCAP/4;
    if (i < z0) ((float4*)g_num)[i] = make_float4(0.f,0.f,0.f,0.f);
    else if (i < z1) ((float4*)g_denom)[i - z0] = make_float4(0.f,0.f,0.f,0.f);
    else if (i < z2) ((int4*)g_perm)[i - z1] = make_int4(-1,-1,-1,-1);
    else if (i < z3) ((int4*)g_nperm)[i - z2] = make_int4(-1,-1,-1,-1);
    if (bid == 0 && tid < RTYPES) { g_counts[tid] = 0; g_cursor[tid] = 0; }
    if (bid == 0 && tid >= 32 && tid < 32 + TTYPES) {
      g_ncounts[tid-32] = 0; g_ncursor[tid-32] = 0;
    }
    return;
  }
  if (bid < NBI + 128) {   // edge-type histogram
    if (tid < RTYPES) loc[tid] = 0;
    __syncthreads();
    for (int i = (bid - NBI)*256 + tid; i < E; i += 128*256)
      atomicAdd(&loc[etype[i]], 1);
    __syncthreads();
    if (tid < RTYPES && loc[tid]) atomicAdd(&g_counts[tid], loc[tid]);
    return;
  }
  if (bid < NBI + 144) {   // node-type histogram
    if (tid < TTYPES) loc[tid] = 0;
    __syncthreads();
    for (int i = (bid - NBI - 128)*256 + tid; i < M; i += 16*256)
      atomicAdd(&loc[ntype[i]], 1);
    __syncthreads();
    if (tid < TTYPES && loc[tid]) atomicAdd(&g_ncounts[tid], loc[tid]);
    return;
  }
  // weight prep (hi only): one task = (r, n, 4 consecutive k) -> one 8B store
  int idx = (bid - NBI - 144) * 256 + tid;
  const float* W; uchar* hbase; int r, n, k0, Kdim, wimg;
  if (idx < 32768) {                  // Wq: 8r x 128n x 32kg
    r = idx >> 12; int rem = idx & 4095; k0 = (rem >> 7) * 4; n = rem & 127;
    W = Wq + r*16384; hbase = g_Bq + r*32768; Kdim = 128;
  } else if (idx < 32768 + 49152) {   // Wk: 8r x 128n x 48kg
    int i2 = idx - 32768;
    r = i2 / 6144; int rem = i2 % 6144; k0 = (rem >> 7) * 4; n = rem & 127;
    W = Wk + r*20480; hbase = g_Bk + r*49152; Kdim = 160;
  } else if (idx < 32768 + 2*49152) { // Wv
    int i3 = idx - 32768 - 49152;
    r = i3 / 6144; int rem = i3 % 6144; k0 = (rem >> 7) * 4; n = rem & 127;
    W = Wv + r*20480; hbase = g_Bv + r*49152; Kdim = 160;
  } else return;
  unsigned short h[4];
#pragma unroll
  for (int i = 0; i < 4; ++i) {
    int k = k0 + i;
    h[i] = hbits((k < Kdim) ? W[k*128 + n] : 0.f);
  }
  *(uint2*)(hbase + koff(n, k0)) =
      make_uint2((uint32_t)h[0] | ((uint32_t)h[1]<<16),
                 (uint32_t)h[2] | ((uint32_t)h[3]<<16));
}

// ============ merged edge + node scatter (inline prefix scans) ============
__global__ void k_scatter(const int* __restrict__ etype, int E,
                          const int* __restrict__ ntype, int M, int EB) {
  __shared__ int loc[RTYPES], base[RTYPES], pf[RTYPES];
  const int t = threadIdx.x;
  if ((int)blockIdx.x < EB) {   // edges
    if (t < RTYPES) loc[t] = 0;
    __syncthreads();
    const int start = blockIdx.x * 1024;
    const int end = min(start + 1024, E);
    for (int i = start + t; i < end; i += 256) atomicAdd(&loc[etype[i]], 1);
    if (t == 0) {
      int b = 0;
      for (int r = 0; r < RTYPES; ++r) {
        pf[r] = b;
        b += ((g_counts[r] + CSZ - 1) / CSZ) * CSZ;
      }
    }
    __syncthreads();
    if (t < RTYPES) {
      base[t] = pf[t] + (loc[t] ? atomicAdd(&g_cursor[t], loc[t]) : 0);
      loc[t] = 0;
    }
    __syncthreads();
    for (int i = start + t; i < end; i += 256) {
      int r = etype[i];
      g_perm[base[r] + atomicAdd(&loc[r], 1)] = i;
    }
  } else {                       // nodes
    if (t < TTYPES) loc[t] = 0;
    __syncthreads();
    const int start = (blockIdx.x - EB) * 1024;
    const int end = min(start + 1024, M);
    for (int i = start + t; i < end; i += 256) atomicAdd(&loc[ntype[i]], 1);
    if (t == 0) {
      int b = 0;
      for (int r = 0; r < TTYPES; ++r) {
        pf[r] = b;
        b += ((g_ncounts[r] + 63) / 64) * 64;
      }
    }
    __syncthreads();
    if (t < TTYPES) {
      base[t] = pf[t] + (loc[t] ? atomicAdd(&g_ncursor[t], loc[t]) : 0);
      loc[t] = 0;
    }
    __syncthreads();
    for (int i = start + t; i < end; i += 256) {
      int r = ntype[i];
      g_nperm[base[r] + atomicAdd(&loc[r], 1)] = i;
    }
  }
}

// ======== main edge kernel: fp16 1/1/2-pass MMA, fully hidden staging =====
__global__ void __launch_bounds__(512, 1) k_edge(
    const float* __restrict__ src_h, const float* __restrict__ src_tw,
    const float* __restrict__ src_tb, const float* __restrict__ edge_h,
    const float* __restrict__ date, const int* __restrict__ src_idx,
    const int* __restrict__ dst_idx, const int* __restrict__ etype,
    const float* __restrict__ sg, const float* __restrict__ sb,
    const float* __restrict__ dg, const float* __restrict__ db)
{
  extern __shared__ __align__(1024) char sm[];
  __half* sEx = (__half*)(sm + OFF_EX);
  int*    sDst = (int*)(sm + OFF_DST);
  const uint32_t smb = (uint32_t)__cvta_generic_to_shared(sm);

  const int tid = threadIdx.x, wid = tid >> 5, lane = tid & 31;
  const int cbase = blockIdx.x * CSZ;

  const int e0 = g_perm[cbase];
  if (e0 < 0) return;           // pure-padding chunk
  const int et = etype[e0];

  // C1: Bq_hi -> B1 (32KB); C2: Bk_hi -> B2 (48KB); both during LN
  { const uchar* b = g_Bq + et*32768;
    for (int o = tid*16; o < 32768; o += 8192) cp16(smb + OFF_B1 + o, b + o); }
  CP_COMMIT();
  { const uchar* b = g_Bk + et*49152;
    for (int o = tid*16; o < 49152; o += 8192) cp16(smb + OFF_B2 + o, b + o); }
  CP_COMMIT();

  if (tid < CSZ) {
    int e = g_perm[cbase + tid];
    sDst[tid] = (e >= 0) ? dst_idx[e] : -1;
  }
  __syncthreads();

  // ------- Phase A: software-pipelined gather + LN -> fp16 SMEM ----------
  {
    int eN = g_perm[cbase + wid];
    float tN=0.f, xdN0=0,xdN1=0,xdN2=0,xdN3=0, twdN=0, tbdN=0;
    float xsN0=0,xsN1=0,xsN2=0,xsN3=0, twsN=0, tbsN=0, ehN=0;
    if (eN >= 0) {
      tN = date[eN];
      int s = src_idx[eN], d = sDst[wid];
      xdN0 = src_h[d*128+lane];    xdN1 = src_h[d*128+lane+32];
      xdN2 = src_h[d*128+lane+64]; xdN3 = src_h[d*128+lane+96];
      twdN = src_tw[d*32+lane];    tbdN = src_tb[d*32+lane];
      xsN0 = src_h[s*128+lane];    xsN1 = src_h[s*128+lane+32];
      xsN2 = src_h[s*128+lane+64]; xsN3 = src_h[s*128+lane+96];
      twsN = src_tw[s*32+lane];    tbsN = src_tb[s*32+lane];
      ehN  = edge_h[eN*32+lane];
    }
#pragma unroll
    for (int j = 0; j < 8; ++j) {
      const int c = wid + 16*j;
      const int e = eN;
      float t = tN;
      float xd0=xdN0, xd1=xdN1, xd2=xdN2, xd3=xdN3, twd=twdN, tbd=tbdN;
      float xs0=xsN0, xs1=xsN1, xs2=xsN2, xs3=xsN3, tws=twsN, tbs=tbsN, eh=ehN;
      if (j < 7) {                      // issue next row's loads now (MLP)
        const int cN = wid + 16*(j+1);
        eN = g_perm[cbase + cN];
        if (eN >= 0) {
          tN = date[eN];
          int s = src_idx[eN], d = sDst[cN];
          xdN0 = src_h[d*128+lane];    xdN1 = src_h[d*128+lane+32];
          xdN2 = src_h[d*128+lane+64]; xdN3 = src_h[d*128+lane+96];
          twdN = src_tw[d*32+lane];    tbdN = src_tb[d*32+lane];
          xsN0 = src_h[s*128+lane];    xsN1 = src_h[s*128+lane+32];
          xsN2 = src_h[s*128+lane+64]; xsN3 = src_h[s*128+lane+96];
          twsN = src_tw[s*32+lane];    tbsN = src_tb[s*32+lane];
          ehN  = edge_h[eN*32+lane];
        }
      }
      if (e < 0) continue;   // pad row: stale SMEM is row-local, guarded later

      // dst LN (fused moments), fp16 hi only
      xd0 *= __sinf(twd*t + tbd);
      {
        float s1 = ((xd0+xd1)+(xd2+xd3));
        float s2 = fmaf(xd0,xd0, fmaf(xd1,xd1, fmaf(xd2,xd2, xd3*xd3)));
#pragma unroll
        for (int o = 16; o; o >>= 1) {
          s1 += __shfl_xor_sync(0xffffffffu, s1, o);
          s2 += __shfl_xor_sync(0xffffffffu, s2, o);
        }
        float mu = s1 * (1.f/128.f);
        float rs = rsqrtf(fmaf(-mu, mu, s2*(1.f/128.f)) + 1e-5f);
        float vout[4] = {xd0, xd1, xd2, xd3};
#pragma unroll
        for (int kk = 0; kk < 4; ++kk) {
          int i = lane + 32*kk;
          float v = (vout[kk]-mu)*rs*dg[i] + db[i];
          *(unsigned short*)(sm + OFF_AD + koff(c, i)) = hbits(v);
        }
      }
      // src LN (160 dims), fp16 hi + lo (compensates v GEMM)
      xs0 *= __sinf(tws*t + tbs);
      {
        float s1 = (((xs0+xs1)+(xs2+xs3))+eh);
        float s2 = fmaf(xs0,xs0, fmaf(xs1,xs1, fmaf(xs2,xs2, fmaf(xs3,xs3, eh*eh))));
#pragma unroll
        for (int o = 16; o; o >>= 1) {
          s1 += __shfl_xor_sync(0xffffffffu, s1, o);
          s2 += __shfl_xor_sync(0xffffffffu, s2, o);
        }
        float mu = s1 * (1.f/160.f);
        float rs = rsqrtf(fmaf(-mu, mu, s2*(1.f/160.f)) + 1e-5f);
        float vout[5] = {xs0, xs1, xs2, xs3, eh};
#pragma unroll
        for (int kk = 0; kk < 5; ++kk) {
          int i = lane + 32*kk;
          float v = (vout[kk]-mu)*rs*sg[i] + sb[i];
          __half hh = __float2half_rn(v);
          uint32_t o2 = koff(c, i);
          *(__half*)(sm + OFF_AS_HI + o2) = hh;
          *(__half*)(sm + OFF_AS_LO + o2) = __float2half_rn(v - __half2float(hh));
        }
        uint32_t o2 = koff(c, 160 + lane);   // K-pad [160,192)
        *(unsigned short*)(sm + OFF_AS_HI + o2) = 0;
        *(unsigned short*)(sm + OFF_AS_LO + o2) = 0;
      }
    }
  }
  CP_WAIT1();          // B1 (Bq) ready; B2 may still be in flight
  __syncthreads();

  const int m0 = (wid >> 2) * 32;
  const int n0 = (wid & 3) * 32;

  // ---- q GEMM: single fp16 pass ----
  float accQ[2][4][4];
#pragma unroll
  for (int a = 0; a < 2; ++a)
#pragma unroll
    for (int b = 0; b < 4; ++b)
#pragma unroll
      for (int cc = 0; cc < 4; ++cc) accQ[a][b][cc] = 0.f;
  gemm_pass<8,2>(smb + OFF_AD, smb + OFF_B1, m0, n0, lane, accQ);
  __syncthreads();     // all reads of B1 done

  // C3: Bv_hi -> B1 (overlaps k GEMM)
  { const uchar* b = g_Bv + et*49152;
    for (int o = tid*16; o < 49152; o += 8192) cp16(smb + OFF_B1 + o, b + o); }
  CP_COMMIT();
  CP_WAIT1();          // ensures C2 (Bk) done; C3 may pend
  __syncthreads();

  // ---- k GEMM: single fp16 pass, full 32-col tile ----
  float accC[2][4][4];
#pragma unroll
  for (int a = 0; a < 2; ++a)
#pragma unroll
    for (int b = 0; b < 4; ++b)
#pragma unroll
      for (int cc = 0; cc < 4; ++cc) accC[a][b][cc] = 0.f;
  gemm_pass<10,2>(smb + OFF_AS_HI, smb + OFF_B2, m0, n0, lane, accC);

  // ---- logits: per-head q.k dots; exp; fp16 ex; denominators ----
  const float scl = 0.0883883476483184f;  // 1/sqrt(128)
#pragma unroll
  for (int h = 0; h < 2; ++h) {
    const int head = (n0 >> 4) + h;
#pragma unroll
    for (int mi = 0; mi < 2; ++mi)
#pragma unroll
      for (int rh = 0; rh < 2; ++rh) {
        float p = 0.f;
#pragma unroll
        for (int nj = 0; nj < 2; ++nj) {
          p = fmaf(accQ[mi][2*h+nj][2*rh],   accC[mi][2*h+nj][2*rh],   p);
          p = fmaf(accQ[mi][2*h+nj][2*rh+1], accC[mi][2*h+nj][2*rh+1], p);
        }
        p += __shfl_xor_sync(0xffffffffu, p, 1);
        p += __shfl_xor_sync(0xffffffffu, p, 2);
        if ((lane & 3) == 0) {
          int row = m0 + mi*16 + rh*8 + (lane >> 2);
          __half exh = __float2half_rn(__expf(p * scl));
          sEx[row*8 + head] = exh;
          int d = sDst[row];
          if (d >= 0) atomicAdd(&g_denom[d*8 + head], __half2float(exh));
        }
      }
  }
  CP_WAIT0();          // Bv ready
  __syncthreads();

  // ---- v GEMM: 2 passes (A_s hi + lo vs Bv_hi) ----
  float accV[2][4][4];
#pragma unroll
  for (int a = 0; a < 2; ++a)
#pragma unroll
    for (int b = 0; b < 4; ++b)
#pragma unroll
      for (int cc = 0; cc < 4; ++cc) accV[a][b][cc] = 0.f;
  gemm_pass<10,2>(smb + OFF_AS_HI, smb + OFF_B1, m0, n0, lane, accV);
  gemm_pass<10,2>(smb + OFF_AS_LO, smb + OFF_B1, m0, n0, lane, accV);
  __syncthreads();     // A_s reads done -> reuse as bounce

  // ---- epilogue: scale by ex -> xor-swizzled bounce -> red.v4 scatter ----
  {
    float* bounce = (float*)(sm + OFF_AS_HI);  // 64KB, col ^ ((row&7)<<2)
#pragma unroll
    for (int mi = 0; mi < 2; ++mi)
#pragma unroll
      for (int nj = 0; nj < 4; ++nj) {
        int col = n0 + nj*8 + (lane & 3)*2;
        int head = (n0 >> 4) + (nj >> 1);
        int row0 = m0 + mi*16 + (lane >> 2);
        int row1 = row0 + 8;
        float ex0 = __half2float(sEx[row0*8 + head]);
        float ex1 = __half2float(sEx[row1*8 + head]);
        *(float2*)&bounce[row0*128 + (col ^ ((row0 & 7) << 2))] =
            make_float2(accV[mi][nj][0]*ex0, accV[mi][nj][1]*ex0);
        *(float2*)&bounce[row1*128 + (col ^ ((row1 & 7) << 2))] =
            make_float2(accV[mi][nj][2]*ex1, accV[mi][nj][3]*ex1);
      }
  }
  __syncthreads();
  {
    const float* bounce = (const float*)(sm + OFF_AS_HI);
#pragma unroll
    for (int i = 0; i < 8; ++i) {
      int e = wid*8 + i;
      int d = sDst[e];
      if (d < 0) continue;
      int col = (lane*4) ^ ((e & 7) << 2);
      float4 v = *(const float4*)&bounce[e*128 + col];
      red4(&g_num[d*128 + (lane*4)], v);
    }
  }
}

// ====== output kernel: type-pure 64-node chunks, 4 nodes in flight ========
__global__ void __launch_bounds__(512) k_out(
    const float* __restrict__ src_h, const int* __restrict__ ntype,
    const float* __restrict__ Wa, const float* __restrict__ h_bias,
    const float* __restrict__ skip, float* __restrict__ out)
{
  extern __shared__ float smem[];
  float* sWa = smem;              // 128x128
  float* sh  = smem + 16384;      // 4x128
  const int tid = threadIdx.x, col = tid & 127, quad = tid >> 7;
  const int m0 = g_nperm[blockIdx.x * 64];
  if (m0 < 0) return;             // pad-only chunk
  const int tt = ntype[m0];
  {
    const uchar* w = (const uchar*)(Wa + tt*16384);
    uint32_t dst = (uint32_t)__cvta_generic_to_shared(sWa);
    for (int o = tid*16; o < 65536; o += 8192) cp16(dst + o, w + o);
    CP_COMMIT();
  }
  const float gate = 1.f / (1.f + __expf(-skip[tt]));
  const float bias = h_bias[tt*128 + col];
  CP_WAIT0();
  __syncthreads();

  for (int it = 0; it < 16; ++it) {
    const int m = g_nperm[blockIdx.x*64 + it*4 + quad];
    if (m >= 0) {
      float dden = g_denom[m*8 + (col >> 4)];
      float hv = (dden > 0.f) ? g_num[m*128 + col] / dden : 0.f;
      sh[quad*128 + col] = hv + bias;
    }
    __syncthreads();
    float a0 = 0.f, a1 = 0.f, a2 = 0.f, a3 = 0.f;
    const float* shh = sh + quad*128;
#pragma unroll
    for (int i = 0; i < 128; i += 4) {
      a0 = fmaf(shh[i+0], sWa[(i+0)*128 + col], a0);
      a1 = fmaf(shh[i+1], sWa[(i+1)*128 + col], a1);
      a2 = fmaf(shh[i+2], sWa[(i+2)*128 + col], a2);
      a3 = fmaf(shh[i+3], sWa[(i+3)*128 + col], a3);
    }
    if (m >= 0)
      out[m*128 + col] = ((a0+a1)+(a2+a3))*gate + src_h[m*128 + col]*(1.f - gate);
    __syncthreads();
  }
}

extern "C" void kernel_launch(void* const* d_in, const int* in_sizes, int n_in,
                              void* d_out, int out_size) {
  const float* src_h  = (const float*)d_in[0];
  const float* src_tw = (const float*)d_in[1];
  const float* src_tb = (const float*)d_in[2];
  const float* edge_h = (const float*)d_in[3];
  const float* date   = (const float*)d_in[4];
  const int*   src_idx= (const int*)d_in[5];
  const int*   dst_idx= (const int*)d_in[6];
  const int*   etype  = (const int*)d_in[7];
  const int*   ntype  = (const int*)d_in[8];
  const float* Wq     = (const float*)d_in[9];
  const float* Wk     = (const float*)d_in[10];
  const float* Wv     = (const float*)d_in[11];
  const float* Wa     = (const float*)d_in[12];
  const float* h_bias = (const float*)d_in[13];
  const float* skip   = (const float*)d_in[14];
  const float* sg     = (const float*)d_in[15];
  const float* sb     = (const float*)d_in[16];
  const float* dg     = (const float*)d_in[17];
  const float* db     = (const float*)d_in[18];
  float* out = (float*)d_out;

  const int E = in_sizes[4];
  const int M = in_sizes[8];
  const int NB = (E + CSZ - 1)/CSZ + RTYPES;
  const int NNB = (M + 63)/64 + TTYPES;
  const int EB = (E + 1023)/1024;
  const int MB = (M + 1023)/1024;

  cudaFuncSetAttribute(k_edge, cudaFuncAttributeMaxDynamicSharedMemorySize, SMEM_EDGE);
  cudaFuncSetAttribute(k_out, cudaFuncAttributeMaxDynamicSharedMemorySize, (16384+512)*4);

  const int initTasks = M*32 + M*2 + PCAP/4 + NPCAP/4;
  const int NBI = (initTasks + 255) / 256;
  const int NBP = (32768 + 2*49152 + 255) / 256;   // 512
  k_prep<<<NBI + 144 + NBP, 256>>>(etype, ntype, E, M, Wq, Wk, Wv, NBI);
  k_scatter<<<EB + MB, 256>>>(etype, E, ntype, M, EB);
  k_edge<<<NB, 512, SMEM_EDGE>>>(src_h, src_tw, src_tb, edge_h, date,
                                 src_idx, dst_idx, etype, sg, sb, dg, db);
  k_out<<<NNB, 512, (16384+512)*4>>>(src_h, ntype, Wa, h_bias, skip, out);
}

// round 14
// speedup vs baseline: 2.7040x; 2.2635x over previous
#include <cuda_runtime.h>
#include <cuda_fp16.h>
#include <cstdint>

#define RTYPES 8
#define TTYPES 4
#define CSZ 128
#define MCAP 10000
#define ECAP 100000
#define PCAP (ECAP + (RTYPES + 1) * CSZ)
#define NPCAP (MCAP + TTYPES*64)

// ---------------- device scratch (no runtime alloc allowed) ----------------
__device__ float g_num[MCAP*128];
__device__ float g_denom[MCAP*8];
__device__ int   g_perm[PCAP];
__device__ int   g_counts[RTYPES];
__device__ int   g_cursor[RTYPES];
__device__ int   g_nperm[NPCAP];
__device__ int   g_ncounts[TTYPES];
__device__ int   g_ncursor[TTYPES];
// Pre-swizzled fp16 weight images (hi only; K-major blocked atoms + xor swizzle)
__device__ __align__(128) unsigned char g_Bq[RTYPES*32768];
__device__ __align__(128) unsigned char g_Bk[RTYPES*49152];
__device__ __align__(128) unsigned char g_Bv[RTYPES*49152];
__device__ __align__(128) unsigned char g_Ba[TTYPES*32768];

// ---------------- SMEM byte layout for k_edge (231936 total) ----------------
#define OFF_AD    0          // 32768  A_d fp16 (hi only; q is 1-pass)
#define OFF_AS_HI 32768      // 49152
#define OFF_AS_LO 81920      // 49152
#define OFF_B1    131072     // 49152  (Bq_hi 32K, later Bv_hi 48K)
#define OFF_B2    180224     // 49152  (Bk_hi)
#define OFF_EX    229376     // half[128*8] = 2048
#define OFF_DST   231424     // int[128]   = 512
#define SMEM_EDGE 231936

// ---------------- SMEM byte layout for k_out (98560 total) ------------------
#define O_AH 0               // 32768 (64 rows used)
#define O_AL 32768           // 32768
#define O_B  65536           // 32768 Wa image
#define O_ND 98304           // int[64]
#define SMEM_OUT 98560

typedef unsigned char uchar;

// blocked-atom K-major byte offset: atom = 8 rows x 64 fp16 (1024B),
// 16 m-atoms, k-atoms stride 16KB; xor swizzle for conflict-free ldsm.
__host__ __device__ __forceinline__ uint32_t koff(int m, int k) {
  uint32_t off = (uint32_t)(((m >> 3) + (k >> 6) * 16) * 1024 + (m & 7) * 128 + (k & 63) * 2);
  return off ^ ((off >> 3) & 0x70);
}
__device__ __forceinline__ uint32_t koff2(uint32_t rowbase, int k) {
  uint32_t off = rowbase + ((k >> 6) << 14) + ((k & 63) << 1);
  return off ^ ((off >> 3) & 0x70);
}

__device__ __forceinline__ void cp16(uint32_t dst, const void* src) {
  asm volatile("cp.async.cg.shared.global [%0], [%1], 16;" :: "r"(dst), "l"(src));
}
#define CP_COMMIT() asm volatile("cp.async.commit_group;")
#define CP_WAIT0()  asm volatile("cp.async.wait_group 0;")
#define CP_WAIT1()  asm volatile("cp.async.wait_group 1;")

__device__ __forceinline__ void ldsm4(uint32_t* r, uint32_t a) {
  asm volatile("ldmatrix.sync.aligned.m8n8.x4.shared.b16 {%0,%1,%2,%3}, [%4];"
    : "=r"(r[0]), "=r"(r[1]), "=r"(r[2]), "=r"(r[3]) : "r"(a));
}
__device__ __forceinline__ void mma16816(float* c, const uint32_t* a, const uint32_t* b) {
  asm volatile("mma.sync.aligned.m16n8k16.row.col.f32.f16.f16.f32 "
    "{%0,%1,%2,%3}, {%4,%5,%6,%7}, {%8,%9}, {%0,%1,%2,%3};"
    : "+f"(c[0]), "+f"(c[1]), "+f"(c[2]), "+f"(c[3])
    : "r"(a[0]), "r"(a[1]), "r"(a[2]), "r"(a[3]), "r"(b[0]), "r"(b[1]));
}
__device__ __forceinline__ void red4(float* p, float4 v) {
  asm volatile("red.global.add.v4.f32 [%0], {%1,%2,%3,%4};"
    :: "l"(p), "f"(v.x), "f"(v.y), "f"(v.z), "f"(v.w) : "memory");
}
__device__ __forceinline__ unsigned short hbits(float v) {
  __half h = __float2half_rn(v);
  return *(unsigned short*)&h;
}

// One pass: C[32 x NT*16] += A[32xK] @ B[.xK]^T for one warp tile (m0, nb0).
template<int NK, int NT>
__device__ __forceinline__ void gemm_pass(
    uint32_t aB, uint32_t bB, int m0, int nb0, int lane,
    float (&acc)[2][2*NT][4])
{
  const int r0 = m0 + (lane & 15);
  const int r1 = r0 + 16;
  const uint32_t arb0 = (uint32_t)(((r0 >> 3) << 10) + ((r0 & 7) << 7));
  const uint32_t arb1 = (uint32_t)(((r1 >> 3) << 10) + ((r1 & 7) << 7));
  const int ak = (lane >> 4) << 3;
  const int bn = nb0 + (lane & 7) + ((lane >> 4) << 3);
  const int bk = ((lane >> 3) & 1) << 3;
  uint32_t brb[NT];
#pragma unroll
  for (int p = 0; p < NT; ++p) {
    int n = bn + p * 16;
    brb[p] = (uint32_t)(((n >> 3) << 10) + ((n & 7) << 7));
  }
#pragma unroll
  for (int ks = 0; ks < NK; ++ks) {
    const int k0 = ks << 4;
    uint32_t A0[4], A1[4], B[NT][4];
    ldsm4(A0, aB + koff2(arb0, k0 + ak));
    ldsm4(A1, aB + koff2(arb1, k0 + ak));
#pragma unroll
    for (int p = 0; p < NT; ++p) ldsm4(B[p], bB + koff2(brb[p], k0 + bk));
#pragma unroll
    for (int p = 0; p < NT; ++p) {
      mma16816(acc[0][2*p],   A0, &B[p][0]);
      mma16816(acc[0][2*p+1], A0, &B[p][2]);
      mma16816(acc[1][2*p],   A1, &B[p][0]);
      mma16816(acc[1][2*p+1], A1, &B[p][2]);
    }
  }
}

// ====== fused init + edge-count + node-count + weight-image prep ==========
__global__ void __launch_bounds__(256) k_prep(
    const int* __restrict__ etype, const int* __restrict__ ntype, int E, int M,
    const float* __restrict__ Wq, const float* __restrict__ Wk,
    const float* __restrict__ Wv, const float* __restrict__ Wa, int NBI)
{
  __shared__ int loc[RTYPES];
  const int bid = blockIdx.x, tid = threadIdx.x;
  if (bid < NBI) {   // vectorized init
    int i = bid * 256 + tid;
    const int z0 = M*32, z1 = z0 + M*2, z2 = z1 + PCAP/4, z3 = z2 + NPCAP/4;
    if (i < z0) ((float4*)g_num)[i] = make_float4(0.f,0.f,0.f,0.f);
    else if (i < z1) ((float4*)g_denom)[i - z0] = make_float4(0.f,0.f,0.f,0.f);
    else if (i < z2) ((int4*)g_perm)[i - z1] = make_int4(-1,-1,-1,-1);
    else if (i < z3) ((int4*)g_nperm)[i - z2] = make_int4(-1,-1,-1,-1);
    if (bid == 0 && tid < RTYPES) { g_counts[tid] = 0; g_cursor[tid] = 0; }
    if (bid == 0 && tid >= 32 && tid < 32 + TTYPES) {
      g_ncounts[tid-32] = 0; g_ncursor[tid-32] = 0;
    }
    return;
  }
  if (bid < NBI + 128) {   // edge-type histogram
    if (tid < RTYPES) loc[tid] = 0;
    __syncthreads();
    for (int i = (bid - NBI)*256 + tid; i < E; i += 128*256)
      atomicAdd(&loc[etype[i]], 1);
    __syncthreads();
    if (tid < RTYPES && loc[tid]) atomicAdd(&g_counts[tid], loc[tid]);
    return;
  }
  if (bid < NBI + 144) {   // node-type histogram
    if (tid < TTYPES) loc[tid] = 0;
    __syncthreads();
    for (int i = (bid - NBI - 128)*256 + tid; i < M; i += 16*256)
      atomicAdd(&loc[ntype[i]], 1);
    __syncthreads();
    if (tid < TTYPES && loc[tid]) atomicAdd(&g_ncounts[tid], loc[tid]);
    return;
  }
  // weight prep (hi only): one task = (r, n, 4 consecutive k) -> one 8B store
  int idx = (bid - NBI - 144) * 256 + tid;
  const float* W; uchar* hbase; int r, n, k0, Kdim;
  if (idx < 32768) {                  // Wq: 8r x 128n x 32kg
    r = idx >> 12; int rem = idx & 4095; k0 = (rem >> 7) * 4; n = rem & 127;
    W = Wq + r*16384; hbase = g_Bq + r*32768; Kdim = 128;
  } else if (idx < 32768 + 49152) {   // Wk: 8r x 128n x 48kg
    int i2 = idx - 32768;
    r = i2 / 6144; int rem = i2 % 6144; k0 = (rem >> 7) * 4; n = rem & 127;
    W = Wk + r*20480; hbase = g_Bk + r*49152; Kdim = 160;
  } else if (idx < 32768 + 2*49152) { // Wv
    int i3 = idx - 32768 - 49152;
    r = i3 / 6144; int rem = i3 % 6144; k0 = (rem >> 7) * 4; n = rem & 127;
    W = Wv + r*20480; hbase = g_Bv + r*49152; Kdim = 160;
  } else if (idx < 32768 + 2*49152 + 16384) {  // Wa: 4t x 128n x 32kg
    int i4 = idx - 32768 - 2*49152;
    r = i4 >> 12; int rem = i4 & 4095; k0 = (rem >> 7) * 4; n = rem & 127;
    W = Wa + r*16384; hbase = g_Ba + r*32768; Kdim = 128;
  } else return;
  unsigned short h[4];
#pragma unroll
  for (int i = 0; i < 4; ++i) {
    int k = k0 + i;
    h[i] = hbits((k < Kdim) ? W[k*128 + n] : 0.f);
  }
  *(uint2*)(hbase + koff(n, k0)) =
      make_uint2((uint32_t)h[0] | ((uint32_t)h[1]<<16),
                 (uint32_t)h[2] | ((uint32_t)h[3]<<16));
}

// ============ merged edge + node scatter (inline prefix scans) ============
__global__ void k_scatter(const int* __restrict__ etype, int E,
                          const int* __restrict__ ntype, int M, int EB) {
  __shared__ int loc[RTYPES], base[RTYPES], pf[RTYPES];
  const int t = threadIdx.x;
  if ((int)blockIdx.x < EB) {   // edges
    if (t < RTYPES) loc[t] = 0;
    __syncthreads();
    const int start = blockIdx.x * 1024;
    const int end = min(start + 1024, E);
    for (int i = start + t; i < end; i += 256) atomicAdd(&loc[etype[i]], 1);
    if (t == 0) {
      int b = 0;
      for (int r = 0; r < RTYPES; ++r) {
        pf[r] = b;
        b += ((g_counts[r] + CSZ - 1) / CSZ) * CSZ;
      }
    }
    __syncthreads();
    if (t < RTYPES) {
      base[t] = pf[t] + (loc[t] ? atomicAdd(&g_cursor[t], loc[t]) : 0);
      loc[t] = 0;
    }
    __syncthreads();
    for (int i = start + t; i < end; i += 256) {
      int r = etype[i];
      g_perm[base[r] + atomicAdd(&loc[r], 1)] = i;
    }
  } else {                       // nodes
    if (t < TTYPES) loc[t] = 0;
    __syncthreads();
    const int start = (blockIdx.x - EB) * 1024;
    const int end = min(start + 1024, M);
    for (int i = start + t; i < end; i += 256) atomicAdd(&loc[ntype[i]], 1);
    if (t == 0) {
      int b = 0;
      for (int r = 0; r < TTYPES; ++r) {
        pf[r] = b;
        b += ((g_ncounts[r] + 63) / 64) * 64;
      }
    }
    __syncthreads();
    if (t < TTYPES) {
      base[t] = pf[t] + (loc[t] ? atomicAdd(&g_ncursor[t], loc[t]) : 0);
      loc[t] = 0;
    }
    __syncthreads();
    for (int i = start + t; i < end; i += 256) {
      int r = ntype[i];
      g_nperm[base[r] + atomicAdd(&loc[r], 1)] = i;
    }
  }
}

// ======== main edge kernel: fp16 1/1/2-pass MMA, fully hidden staging =====
__global__ void __launch_bounds__(512, 1) k_edge(
    const float* __restrict__ src_h, const float* __restrict__ src_tw,
    const float* __restrict__ src_tb, const float* __restrict__ edge_h,
    const float* __restrict__ date, const int* __restrict__ src_idx,
    const int* __restrict__ dst_idx, const int* __restrict__ etype,
    const float* __restrict__ sg, const float* __restrict__ sb,
    const float* __restrict__ dg, const float* __restrict__ db)
{
  extern __shared__ __align__(1024) char sm[];
  __half* sEx = (__half*)(sm + OFF_EX);
  int*    sDst = (int*)(sm + OFF_DST);
  const uint32_t smb = (uint32_t)__cvta_generic_to_shared(sm);

  const int tid = threadIdx.x, wid = tid >> 5, lane = tid & 31;
  const int cbase = blockIdx.x * CSZ;

  const int e0 = g_perm[cbase];
  if (e0 < 0) return;           // pure-padding chunk
  const int et = etype[e0];

  // C1: Bq_hi -> B1 (32KB); C2: Bk_hi -> B2 (48KB); both during LN
  { const uchar* b = g_Bq + et*32768;
    for (int o = tid*16; o < 32768; o += 8192) cp16(smb + OFF_B1 + o, b + o); }
  CP_COMMIT();
  { const uchar* b = g_Bk + et*49152;
    for (int o = tid*16; o < 49152; o += 8192) cp16(smb + OFF_B2 + o, b + o); }
  CP_COMMIT();

  if (tid < CSZ) {
    int e = g_perm[cbase + tid];
    sDst[tid] = (e >= 0) ? dst_idx[e] : -1;
  }
  __syncthreads();

  // ------- Phase A: software-pipelined gather + LN -> fp16 SMEM ----------
  {
    int eN = g_perm[cbase + wid];
    float tN=0.f, xdN0=0,xdN1=0,xdN2=0,xdN3=0, twdN=0, tbdN=0;
    float xsN0=0,xsN1=0,xsN2=0,xsN3=0, twsN=0, tbsN=0, ehN=0;
    if (eN >= 0) {
      tN = date[eN];
      int s = src_idx[eN], d = sDst[wid];
      xdN0 = src_h[d*128+lane];    xdN1 = src_h[d*128+lane+32];
      xdN2 = src_h[d*128+lane+64]; xdN3 = src_h[d*128+lane+96];
      twdN = src_tw[d*32+lane];    tbdN = src_tb[d*32+lane];
      xsN0 = src_h[s*128+lane];    xsN1 = src_h[s*128+lane+32];
      xsN2 = src_h[s*128+lane+64]; xsN3 = src_h[s*128+lane+96];
      twsN = src_tw[s*32+lane];    tbsN = src_tb[s*32+lane];
      ehN  = edge_h[eN*32+lane];
    }
#pragma unroll
    for (int j = 0; j < 8; ++j) {
      const int c = wid + 16*j;
      const int e = eN;
      float t = tN;
      float xd0=xdN0, xd1=xdN1, xd2=xdN2, xd3=xdN3, twd=twdN, tbd=tbdN;
      float xs0=xsN0, xs1=xsN1, xs2=xsN2, xs3=xsN3, tws=twsN, tbs=tbsN, eh=ehN;
      if (j < 7) {                      // issue next row's loads now (MLP)
        const int cN = wid + 16*(j+1);
        eN = g_perm[cbase + cN];
        if (eN >= 0) {
          tN = date[eN];
          int s = src_idx[eN], d = sDst[cN];
          xdN0 = src_h[d*128+lane];    xdN1 = src_h[d*128+lane+32];
          xdN2 = src_h[d*128+lane+64]; xdN3 = src_h[d*128+lane+96];
          twdN = src_tw[d*32+lane];    tbdN = src_tb[d*32+lane];
          xsN0 = src_h[s*128+lane];    xsN1 = src_h[s*128+lane+32];
          xsN2 = src_h[s*128+lane+64]; xsN3 = src_h[s*128+lane+96];
          twsN = src_tw[s*32+lane];    tbsN = src_tb[s*32+lane];
          ehN  = edge_h[eN*32+lane];
        }
      }
      if (e < 0) continue;   // pad row: stale SMEM is row-local, guarded later

      // dst LN (fused moments), fp16 hi only
      xd0 *= __sinf(twd*t + tbd);
      {
        float s1 = ((xd0+xd1)+(xd2+xd3));
        float s2 = fmaf(xd0,xd0, fmaf(xd1,xd1, fmaf(xd2,xd2, xd3*xd3)));
#pragma unroll
        for (int o = 16; o; o >>= 1) {
          s1 += __shfl_xor_sync(0xffffffffu, s1, o);
          s2 += __shfl_xor_sync(0xffffffffu, s2, o);
        }
        float mu = s1 * (1.f/128.f);
        float rs = rsqrtf(fmaf(-mu, mu, s2*(1.f/128.f)) + 1e-5f);
        float vout[4] = {xd0, xd1, xd2, xd3};
#pragma unroll
        for (int kk = 0; kk < 4; ++kk) {
          int i = lane + 32*kk;
          float v = (vout[kk]-mu)*rs*dg[i] + db[i];
          *(unsigned short*)(sm + OFF_AD + koff(c, i)) = hbits(v);
        }
      }
      // src LN (160 dims), fp16 hi + lo (compensates v GEMM)
      xs0 *= __sinf(tws*t + tbs);
      {
        float s1 = (((xs0+xs1)+(xs2+xs3))+eh);
        float s2 = fmaf(xs0,xs0, fmaf(xs1,xs1, fmaf(xs2,xs2, fmaf(xs3,xs3, eh*eh))));
#pragma unroll
        for (int o = 16; o; o >>= 1) {
          s1 += __shfl_xor_sync(0xffffffffu, s1, o);
          s2 += __shfl_xor_sync(0xffffffffu, s2, o);
        }
        float mu = s1 * (1.f/160.f);
        float rs = rsqrtf(fmaf(-mu, mu, s2*(1.f/160.f)) + 1e-5f);
        float vout[5] = {xs0, xs1, xs2, xs3, eh};
#pragma unroll
        for (int kk = 0; kk < 5; ++kk) {
          int i = lane + 32*kk;
          float v = (vout[kk]-mu)*rs*sg[i] + sb[i];
          __half hh = __float2half_rn(v);
          uint32_t o2 = koff(c, i);
          *(__half*)(sm + OFF_AS_HI + o2) = hh;
          *(__half*)(sm + OFF_AS_LO + o2) = __float2half_rn(v - __half2float(hh));
        }
        uint32_t o2 = koff(c, 160 + lane);   // K-pad [160,192)
        *(unsigned short*)(sm + OFF_AS_HI + o2) = 0;
        *(unsigned short*)(sm + OFF_AS_LO + o2) = 0;
      }
    }
  }
  CP_WAIT1();          // B1 (Bq) ready; B2 may still be in flight
  __syncthreads();

  const int m0 = (wid >> 2) * 32;
  const int n0 = (wid & 3) * 32;

  // ---- q GEMM: single fp16 pass ----
  float accQ[2][4][4];
#pragma unroll
  for (int a = 0; a < 2; ++a)
#pragma unroll
    for (int b = 0; b < 4; ++b)
#pragma unroll
      for (int cc = 0; cc < 4; ++cc) accQ[a][b][cc] = 0.f;
  gemm_pass<8,2>(smb + OFF_AD, smb + OFF_B1, m0, n0, lane, accQ);
  __syncthreads();     // all reads of B1 done

  // C3: Bv_hi -> B1 (overlaps k GEMM)
  { const uchar* b = g_Bv + et*49152;
    for (int o = tid*16; o < 49152; o += 8192) cp16(smb + OFF_B1 + o, b + o); }
  CP_COMMIT();
  CP_WAIT1();          // ensures C2 (Bk) done; C3 may pend
  __syncthreads();

  // ---- k GEMM: single fp16 pass, full 32-col tile ----
  float accC[2][4][4];
#pragma unroll
  for (int a = 0; a < 2; ++a)
#pragma unroll
    for (int b = 0; b < 4; ++b)
#pragma unroll
      for (int cc = 0; cc < 4; ++cc) accC[a][b][cc] = 0.f;
  gemm_pass<10,2>(smb + OFF_AS_HI, smb + OFF_B2, m0, n0, lane, accC);

  // ---- logits: per-head q.k dots; exp; fp16 ex; denominators ----
  const float scl = 0.0883883476483184f;  // 1/sqrt(128)
#pragma unroll
  for (int h = 0; h < 2; ++h) {
    const int head = (n0 >> 4) + h;
#pragma unroll
    for (int mi = 0; mi < 2; ++mi)
#pragma unroll
      for (int rh = 0; rh < 2; ++rh) {
        float p = 0.f;
#pragma unroll
        for (int nj = 0; nj < 2; ++nj) {
          p = fmaf(accQ[mi][2*h+nj][2*rh],   accC[mi][2*h+nj][2*rh],   p);
          p = fmaf(accQ[mi][2*h+nj][2*rh+1], accC[mi][2*h+nj][2*rh+1], p);
        }
        p += __shfl_xor_sync(0xffffffffu, p, 1);
        p += __shfl_xor_sync(0xffffffffu, p, 2);
        if ((lane & 3) == 0) {
          int row = m0 + mi*16 + rh*8 + (lane >> 2);
          __half exh = __float2half_rn(__expf(p * scl));
          sEx[row*8 + head] = exh;
          int d = sDst[row];
          if (d >= 0) atomicAdd(&g_denom[d*8 + head], __half2float(exh));
        }
      }
  }
  CP_WAIT0();          // Bv ready
  __syncthreads();

  // ---- v GEMM: 2 passes (A_s hi + lo vs Bv_hi) ----
  float accV[2][4][4];
#pragma unroll
  for (int a = 0; a < 2; ++a)
#pragma unroll
    for (int b = 0; b < 4; ++b)
#pragma unroll
      for (int cc = 0; cc < 4; ++cc) accV[a][b][cc] = 0.f;
  gemm_pass<10,2>(smb + OFF_AS_HI, smb + OFF_B1, m0, n0, lane, accV);
  gemm_pass<10,2>(smb + OFF_AS_LO, smb + OFF_B1, m0, n0, lane, accV);
  __syncthreads();     // A_s reads done -> reuse as bounce

  // ---- epilogue: scale by ex -> xor-swizzled bounce -> red.v4 scatter ----
  {
    float* bounce = (float*)(sm + OFF_AS_HI);  // 64KB, col ^ ((row&7)<<2)
#pragma unroll
    for (int mi = 0; mi < 2; ++mi)
#pragma unroll
      for (int nj = 0; nj < 4; ++nj) {
        int col = n0 + nj*8 + (lane & 3)*2;
        int head = (n0 >> 4) + (nj >> 1);
        int row0 = m0 + mi*16 + (lane >> 2);
        int row1 = row0 + 8;
        float ex0 = __half2float(sEx[row0*8 + head]);
        float ex1 = __half2float(sEx[row1*8 + head]);
        *(float2*)&bounce[row0*128 + (col ^ ((row0 & 7) << 2))] =
            make_float2(accV[mi][nj][0]*ex0, accV[mi][nj][1]*ex0);
        *(float2*)&bounce[row1*128 + (col ^ ((row1 & 7) << 2))] =
            make_float2(accV[mi][nj][2]*ex1, accV[mi][nj][3]*ex1);
      }
  }
  __syncthreads();
  {
    const float* bounce = (const float*)(sm + OFF_AS_HI);
#pragma unroll
    for (int i = 0; i < 8; ++i) {
      int e = wid*8 + i;
      int d = sDst[e];
      if (d < 0) continue;
      int col = (lane*4) ^ ((e & 7) << 2);
      float4 v = *(const float4*)&bounce[e*128 + col];
      red4(&g_num[d*128 + (lane*4)], v);
    }
  }
}

// ====== output kernel: MMA over type-pure 64-node chunks ==================
__global__ void __launch_bounds__(256) k_out(
    const float* __restrict__ src_h, const int* __restrict__ ntype,
    const float* __restrict__ h_bias, const float* __restrict__ skip,
    float* __restrict__ out)
{
  extern __shared__ __align__(1024) char sm[];
  int* sNode = (int*)(sm + O_ND);
  const uint32_t smb = (uint32_t)__cvta_generic_to_shared(sm);
  const int tid = threadIdx.x, wid = tid >> 5, lane = tid & 31;

  const int m0n = g_nperm[blockIdx.x * 64];
  if (m0n < 0) return;             // pad-only chunk
  const int tt = ntype[m0n];

  // stage Wa fp16 image (32KB) while we normalize h
  { const uchar* b = g_Ba + tt*32768;
    for (int o = tid*16; o < 32768; o += 4096) cp16(smb + O_B + o, b + o); }
  CP_COMMIT();
  if (tid < 64) sNode[tid] = g_nperm[blockIdx.x*64 + tid];
  __syncthreads();

  // ---- h = num/denom + bias -> fp16 hi/lo A-image (row = node-in-chunk) ----
  {
    const int row = tid >> 2;            // 0..63
    const int q = (tid & 3) * 32;        // col base
    const int m = sNode[row];
    float inv0 = 0.f, inv1 = 0.f;
    if (m >= 0) {
      float d0 = g_denom[m*8 + (q >> 4)];
      float d1 = g_denom[m*8 + (q >> 4) + 1];
      inv0 = (d0 > 0.f) ? 1.f/d0 : 0.f;
      inv1 = (d1 > 0.f) ? 1.f/d1 : 0.f;
    }
#pragma unroll
    for (int cc = 0; cc < 32; cc += 4) {
      int col = q + cc;
      float h0=0.f, h1=0.f, h2=0.f, h3=0.f;
      if (m >= 0) {
        float4 v = *(const float4*)&g_num[m*128 + col];
        float4 b = *(const float4*)&h_bias[tt*128 + col];
        float inv = (cc < 16) ? inv0 : inv1;
        h0 = fmaf(v.x, inv, b.x); h1 = fmaf(v.y, inv, b.y);
        h2 = fmaf(v.z, inv, b.z); h3 = fmaf(v.w, inv, b.w);
      }
      __half hh0 = __float2half_rn(h0), hh1 = __float2half_rn(h1);
      __half hh2 = __float2half_rn(h2), hh3 = __float2half_rn(h3);
      uint32_t o = koff(row, col);       // 8B-aligned, swizzle-uniform run
      *(uint2*)(sm + O_AH + o) = make_uint2(
          (uint32_t)hbits(h0) | ((uint32_t)hbits(h1) << 16),
          (uint32_t)hbits(h2) | ((uint32_t)hbits(h3) << 16));
      *(uint2*)(sm + O_AL + o) = make_uint2(
          (uint32_t)hbits(h0 - __half2float(hh0)) | ((uint32_t)hbits(h1 - __half2float(hh1)) << 16),
          (uint32_t)hbits(h2 - __half2float(hh2)) | ((uint32_t)hbits(h3 - __half2float(hh3)) << 16));
    }
  }
  CP_WAIT0();
  __syncthreads();

  // ---- GEMM 64x128x128: 2 compensated passes; warp tile 32x32 ----
  const int mw = (wid >> 2) * 32;        // 0 or 32
  const int nw = (wid & 3) * 32;
  float accO[2][4][4];
#pragma unroll
  for (int a = 0; a < 2; ++a)
#pragma unroll
    for (int b = 0; b < 4; ++b)
#pragma unroll
      for (int cc = 0; cc < 4; ++cc) accO[a][b][cc] = 0.f;
  gemm_pass<8,2>(smb + O_AH, smb + O_B, mw, nw, lane, accO);
  gemm_pass<8,2>(smb + O_AL, smb + O_B, mw, nw, lane, accO);

  // ---- epilogue: gated blend, direct coalesced STG ----
  const float gate = 1.f / (1.f + __expf(-skip[tt]));
  const float omg = 1.f - gate;
#pragma unroll
  for (int mi = 0; mi < 2; ++mi)
#pragma unroll
    for (int rh = 0; rh < 2; ++rh) {
      int row = mw + mi*16 + rh*8 + (lane >> 2);
      int mm = sNode[row];
      if (mm < 0) continue;
#pragma unroll
      for (int nj = 0; nj < 4; ++nj) {
        int col = nw + nj*8 + (lane & 3)*2;
        float2 s = *(const float2*)&src_h[mm*128 + col];
        float2 o;
        o.x = accO[mi][nj][2*rh]   * gate + s.x * omg;
        o.y = accO[mi][nj][2*rh+1] * gate + s.y * omg;
        *(float2*)&out[mm*128 + col] = o;
      }
    }
}

extern "C" void kernel_launch(void* const* d_in, const int* in_sizes, int n_in,
                              void* d_out, int out_size) {
  const float* src_h  = (const float*)d_in[0];
  const float* src_tw = (const float*)d_in[1];
  const float* src_tb = (const float*)d_in[2];
  const float* edge_h = (const float*)d_in[3];
  const float* date   = (const float*)d_in[4];
  const int*   src_idx= (const int*)d_in[5];
  const int*   dst_idx= (const int*)d_in[6];
  const int*   etype  = (const int*)d_in[7];
  const int*   ntype  = (const int*)d_in[8];
  const float* Wq     = (const float*)d_in[9];
  const float* Wk     = (const float*)d_in[10];
  const float* Wv     = (const float*)d_in[11];
  const float* Wa     = (const float*)d_in[12];
  const float* h_bias = (const float*)d_in[13];
  const float* skip   = (const float*)d_in[14];
  const float* sg     = (const float*)d_in[15];
  const float* sb     = (const float*)d_in[16];
  const float* dg     = (const float*)d_in[17];
  const float* db     = (const float*)d_in[18];
  float* out = (float*)d_out;

  const int E = in_sizes[4];
  const int M = in_sizes[8];
  const int NB = (E + CSZ - 1)/CSZ + RTYPES;
  const int NNB = (M + 63)/64 + TTYPES;
  const int EB = (E + 1023)/1024;
  const int MB = (M + 1023)/1024;

  cudaFuncSetAttribute(k_edge, cudaFuncAttributeMaxDynamicSharedMemorySize, SMEM_EDGE);
  cudaFuncSetAttribute(k_out, cudaFuncAttributeMaxDynamicSharedMemorySize, SMEM_OUT);

  const int initTasks = M*32 + M*2 + PCAP/4 + NPCAP/4;
  const int NBI = (initTasks + 255) / 256;
  const int NBP = (32768 + 2*49152 + 16384 + 255) / 256;   // 576
  k_prep<<<NBI + 144 + NBP, 256>>>(etype, ntype, E, M, Wq, Wk, Wv, Wa, NBI);
  k_scatter<<<EB + MB, 256>>>(etype, E, ntype, M, EB);
  k_edge<<<NB, 512, SMEM_EDGE>>>(src_h, src_tw, src_tb, edge_h, date,
                                 src_idx, dst_idx, etype, sg, sb, dg, db);
  k_out<<<NNB, 256, SMEM_OUT>>>(src_h, ntype, h_bias, skip, out);
}

// round 15
// speedup vs baseline: 3.0655x; 1.1337x over previous
#include <cuda_runtime.h>
#include <cuda_fp16.h>
#include <cstdint>

#define RTYPES 8
#define TTYPES 4
#define CSZ 128
#define MCAP 10000
#define ECAP 100000
#define PCAP (ECAP + (RTYPES + 1) * CSZ)
#define NPCAP (MCAP + TTYPES*64)

// ---------------- device scratch (no runtime alloc allowed) ----------------
__device__ float g_num[MCAP*128];
__device__ float g_denom[MCAP*8];
__device__ int   g_perm[PCAP];
__device__ int   g_counts[RTYPES];
__device__ int   g_cursor[RTYPES];
__device__ int   g_nperm[NPCAP];
__device__ int   g_ncounts[TTYPES];
__device__ int   g_ncursor[TTYPES];
// Pre-swizzled fp16 weight images (hi only; K-major blocked atoms + xor swizzle)
__device__ __align__(128) unsigned char g_Bq[RTYPES*32768];
__device__ __align__(128) unsigned char g_Bk[RTYPES*49152];
__device__ __align__(128) unsigned char g_Bv[RTYPES*49152];
__device__ __align__(128) unsigned char g_Ba[TTYPES*32768];

// ---------------- SMEM byte layout for k_edge (182784 total) ----------------
#define OFF_AD    0          // 32768  A_d fp16
#define OFF_AS_HI 32768      // 49152  A_s fp16 (single image; v is 1-pass now)
#define OFF_B1    81920      // 49152  (Bq_hi 32K, later Bv_hi 48K)
#define OFF_B2    131072     // 49152  (Bk_hi)
#define OFF_EX    180224     // half[128*8] = 2048
#define OFF_DST   182272     // int[128]   = 512
#define SMEM_EDGE 182784
// bounce (128x128 fp32 = 64KB) overlays [0, 65536) = A_d + AS_HI head, both
// dead after the v GEMM (barrier-protected)

// ---------------- SMEM byte layout for k_out (98560 total) ------------------
#define O_AH 0               // 32768 (64 rows used)
#define O_AL 32768           // 32768
#define O_B  65536           // 32768 Wa image
#define O_ND 98304           // int[64]
#define SMEM_OUT 98560

typedef unsigned char uchar;

// blocked-atom K-major byte offset: atom = 8 rows x 64 fp16 (1024B),
// 16 m-atoms, k-atoms stride 16KB; xor swizzle for conflict-free ldsm.
__host__ __device__ __forceinline__ uint32_t koff(int m, int k) {
  uint32_t off = (uint32_t)(((m >> 3) + (k >> 6) * 16) * 1024 + (m & 7) * 128 + (k & 63) * 2);
  return off ^ ((off >> 3) & 0x70);
}
__device__ __forceinline__ uint32_t koff2(uint32_t rowbase, int k) {
  uint32_t off = rowbase + ((k >> 6) << 14) + ((k & 63) << 1);
  return off ^ ((off >> 3) & 0x70);
}

__device__ __forceinline__ void cp16(uint32_t dst, const void* src) {
  asm volatile("cp.async.cg.shared.global [%0], [%1], 16;" :: "r"(dst), "l"(src));
}
#define CP_COMMIT() asm volatile("cp.async.commit_group;")
#define CP_WAIT0()  asm volatile("cp.async.wait_group 0;")
#define CP_WAIT1()  asm volatile("cp.async.wait_group 1;")

__device__ __forceinline__ void ldsm4(uint32_t* r, uint32_t a) {
  asm volatile("ldmatrix.sync.aligned.m8n8.x4.shared.b16 {%0,%1,%2,%3}, [%4];"
    : "=r"(r[0]), "=r"(r[1]), "=r"(r[2]), "=r"(r[3]) : "r"(a));
}
__device__ __forceinline__ void mma16816(float* c, const uint32_t* a, const uint32_t* b) {
  asm volatile("mma.sync.aligned.m16n8k16.row.col.f32.f16.f16.f32 "
    "{%0,%1,%2,%3}, {%4,%5,%6,%7}, {%8,%9}, {%0,%1,%2,%3};"
    : "+f"(c[0]), "+f"(c[1]), "+f"(c[2]), "+f"(c[3])
    : "r"(a[0]), "r"(a[1]), "r"(a[2]), "r"(a[3]), "r"(b[0]), "r"(b[1]));
}
__device__ __forceinline__ void red4(float* p, float4 v) {
  asm volatile("red.global.add.v4.f32 [%0], {%1,%2,%3,%4};"
    :: "l"(p), "f"(v.x), "f"(v.y), "f"(v.z), "f"(v.w) : "memory");
}
__device__ __forceinline__ unsigned short hbits(float v) {
  __half h = __float2half_rn(v);
  return *(unsigned short*)&h;
}

// One pass: C[32 x NT*16] += A[32xK] @ B[.xK]^T for one warp tile (m0, nb0).
template<int NK, int NT>
__device__ __forceinline__ void gemm_pass(
    uint32_t aB, uint32_t bB, int m0, int nb0, int lane,
    float (&acc)[2][2*NT][4])
{
  const int r0 = m0 + (lane & 15);
  const int r1 = r0 + 16;
  const uint32_t arb0 = (uint32_t)(((r0 >> 3) << 10) + ((r0 & 7) << 7));
  const uint32_t arb1 = (uint32_t)(((r1 >> 3) << 10) + ((r1 & 7) << 7));
  const int ak = (lane >> 4) << 3;
  const int bn = nb0 + (lane & 7) + ((lane >> 4) << 3);
  const int bk = ((lane >> 3) & 1) << 3;
  uint32_t brb[NT];
#pragma unroll
  for (int p = 0; p < NT; ++p) {
    int n = bn + p * 16;
    brb[p] = (uint32_t)(((n >> 3) << 10) + ((n & 7) << 7));
  }
#pragma unroll
  for (int ks = 0; ks < NK; ++ks) {
    const int k0 = ks << 4;
    uint32_t A0[4], A1[4], B[NT][4];
    ldsm4(A0, aB + koff2(arb0, k0 + ak));
    ldsm4(A1, aB + koff2(arb1, k0 + ak));
#pragma unroll
    for (int p = 0; p < NT; ++p) ldsm4(B[p], bB + koff2(brb[p], k0 + bk));
#pragma unroll
    for (int p = 0; p < NT; ++p) {
      mma16816(acc[0][2*p],   A0, &B[p][0]);
      mma16816(acc[0][2*p+1], A0, &B[p][2]);
      mma16816(acc[1][2*p],   A1, &B[p][0]);
      mma16816(acc[1][2*p+1], A1, &B[p][2]);
    }
  }
}

// ====== fused init + edge-count + node-count + weight-image prep ==========
__global__ void __launch_bounds__(256) k_prep(
    const int* __restrict__ etype, const int* __restrict__ ntype, int E, int M,
    const float* __restrict__ Wq, const float* __restrict__ Wk,
    const float* __restrict__ Wv, const float* __restrict__ Wa, int NBI)
{
  __shared__ int loc[RTYPES];
  const int bid = blockIdx.x, tid = threadIdx.x;
  if (bid < NBI) {   // vectorized init
    int i = bid * 256 + tid;
    const int z0 = M*32, z1 = z0 + M*2, z2 = z1 + PCAP/4, z3 = z2 + NPCAP/4;
    if (i < z0) ((float4*)g_num)[i] = make_float4(0.f,0.f,0.f,0.f);
    else if (i < z1) ((float4*)g_denom)[i - z0] = make_float4(0.f,0.f,0.f,0.f);
    else if (i < z2) ((int4*)g_perm)[i - z1] = make_int4(-1,-1,-1,-1);
    else if (i < z3) ((int4*)g_nperm)[i - z2] = make_int4(-1,-1,-1,-1);
    if (bid == 0 && tid < RTYPES) { g_counts[tid] = 0; g_cursor[tid] = 0; }
    if (bid == 0 && tid >= 32 && tid < 32 + TTYPES) {
      g_ncounts[tid-32] = 0; g_ncursor[tid-32] = 0;
    }
    return;
  }
  if (bid < NBI + 128) {   // edge-type histogram
    if (tid < RTYPES) loc[tid] = 0;
    __syncthreads();
    for (int i = (bid - NBI)*256 + tid; i < E; i += 128*256)
      atomicAdd(&loc[etype[i]], 1);
    __syncthreads();
    if (tid < RTYPES && loc[tid]) atomicAdd(&g_counts[tid], loc[tid]);
    return;
  }
  if (bid < NBI + 144) {   // node-type histogram
    if (tid < TTYPES) loc[tid] = 0;
    __syncthreads();
    for (int i = (bid - NBI - 128)*256 + tid; i < M; i += 16*256)
      atomicAdd(&loc[ntype[i]], 1);
    __syncthreads();
    if (tid < TTYPES && loc[tid]) atomicAdd(&g_ncounts[tid], loc[tid]);
    return;
  }
  // weight prep (hi only): one task = (r, n, 4 consecutive k) -> one 8B store
  int idx = (bid - NBI - 144) * 256 + tid;
  const float* W; uchar* hbase; int r, n, k0, Kdim;
  if (idx < 32768) {                  // Wq: 8r x 128n x 32kg
    r = idx >> 12; int rem = idx & 4095; k0 = (rem >> 7) * 4; n = rem & 127;
    W = Wq + r*16384; hbase = g_Bq + r*32768; Kdim = 128;
  } else if (idx < 32768 + 49152) {   // Wk: 8r x 128n x 48kg
    int i2 = idx - 32768;
    r = i2 / 6144; int rem = i2 % 6144; k0 = (rem >> 7) * 4; n = rem & 127;
    W = Wk + r*20480; hbase = g_Bk + r*49152; Kdim = 160;
  } else if (idx < 32768 + 2*49152) { // Wv
    int i3 = idx - 32768 - 49152;
    r = i3 / 6144; int rem = i3 % 6144; k0 = (rem >> 7) * 4; n = rem & 127;
    W = Wv + r*20480; hbase = g_Bv + r*49152; Kdim = 160;
  } else if (idx < 32768 + 2*49152 + 16384) {  // Wa: 4t x 128n x 32kg
    int i4 = idx - 32768 - 2*49152;
    r = i4 >> 12; int rem = i4 & 4095; k0 = (rem >> 7) * 4; n = rem & 127;
    W = Wa + r*16384; hbase = g_Ba + r*32768; Kdim = 128;
  } else return;
  unsigned short h[4];
#pragma unroll
  for (int i = 0; i < 4; ++i) {
    int k = k0 + i;
    h[i] = hbits((k < Kdim) ? W[k*128 + n] : 0.f);
  }
  *(uint2*)(hbase + koff(n, k0)) =
      make_uint2((uint32_t)h[0] | ((uint32_t)h[1]<<16),
                 (uint32_t)h[2] | ((uint32_t)h[3]<<16));
}

// ============ merged edge + node scatter (inline prefix scans) ============
__global__ void k_scatter(const int* __restrict__ etype, int E,
                          const int* __restrict__ ntype, int M, int EB) {
  __shared__ int loc[RTYPES], base[RTYPES], pf[RTYPES];
  const int t = threadIdx.x;
  if ((int)blockIdx.x < EB) {   // edges
    if (t < RTYPES) loc[t] = 0;
    __syncthreads();
    const int start = blockIdx.x * 1024;
    const int end = min(start + 1024, E);
    for (int i = start + t; i < end; i += 256) atomicAdd(&loc[etype[i]], 1);
    if (t == 0) {
      int b = 0;
      for (int r = 0; r < RTYPES; ++r) {
        pf[r] = b;
        b += ((g_counts[r] + CSZ - 1) / CSZ) * CSZ;
      }
    }
    __syncthreads();
    if (t < RTYPES) {
      base[t] = pf[t] + (loc[t] ? atomicAdd(&g_cursor[t], loc[t]) : 0);
      loc[t] = 0;
    }
    __syncthreads();
    for (int i = start + t; i < end; i += 256) {
      int r = etype[i];
      g_perm[base[r] + atomicAdd(&loc[r], 1)] = i;
    }
  } else {                       // nodes
    if (t < TTYPES) loc[t] = 0;
    __syncthreads();
    const int start = (blockIdx.x - EB) * 1024;
    const int end = min(start + 1024, M);
    for (int i = start + t; i < end; i += 256) atomicAdd(&loc[ntype[i]], 1);
    if (t == 0) {
      int b = 0;
      for (int r = 0; r < TTYPES; ++r) {
        pf[r] = b;
        b += ((g_ncounts[r] + 63) / 64) * 64;
      }
    }
    __syncthreads();
    if (t < TTYPES) {
      base[t] = pf[t] + (loc[t] ? atomicAdd(&g_ncursor[t], loc[t]) : 0);
      loc[t] = 0;
    }
    __syncthreads();
    for (int i = start + t; i < end; i += 256) {
      int r = ntype[i];
      g_nperm[base[r] + atomicAdd(&loc[r], 1)] = i;
    }
  }
}

// ======== main edge kernel: fp16 1-pass q/k/v MMA, fully hidden staging ===
__global__ void __launch_bounds__(512, 1) k_edge(
    const float* __restrict__ src_h, const float* __restrict__ src_tw,
    const float* __restrict__ src_tb, const float* __restrict__ edge_h,
    const float* __restrict__ date, const int* __restrict__ src_idx,
    const int* __restrict__ dst_idx, const int* __restrict__ etype,
    const float* __restrict__ sg, const float* __restrict__ sb,
    const float* __restrict__ dg, const float* __restrict__ db)
{
  extern __shared__ __align__(1024) char sm[];
  __half* sEx = (__half*)(sm + OFF_EX);
  int*    sDst = (int*)(sm + OFF_DST);
  const uint32_t smb = (uint32_t)__cvta_generic_to_shared(sm);

  const int tid = threadIdx.x, wid = tid >> 5, lane = tid & 31;
  const int cbase = blockIdx.x * CSZ;

  const int e0 = g_perm[cbase];
  if (e0 < 0) return;           // pure-padding chunk
  const int et = etype[e0];

  // C1: Bq_hi -> B1 (32KB); C2: Bk_hi -> B2 (48KB); both during LN
  { const uchar* b = g_Bq + et*32768;
    for (int o = tid*16; o < 32768; o += 8192) cp16(smb + OFF_B1 + o, b + o); }
  CP_COMMIT();
  { const uchar* b = g_Bk + et*49152;
    for (int o = tid*16; o < 49152; o += 8192) cp16(smb + OFF_B2 + o, b + o); }
  CP_COMMIT();

  if (tid < CSZ) {
    int e = g_perm[cbase + tid];
    sDst[tid] = (e >= 0) ? dst_idx[e] : -1;
  }
  __syncthreads();

  // ------- Phase A: software-pipelined gather + LN -> fp16 SMEM ----------
  {
    int eN = g_perm[cbase + wid];
    float tN=0.f, xdN0=0,xdN1=0,xdN2=0,xdN3=0, twdN=0, tbdN=0;
    float xsN0=0,xsN1=0,xsN2=0,xsN3=0, twsN=0, tbsN=0, ehN=0;
    if (eN >= 0) {
      tN = date[eN];
      int s = src_idx[eN], d = sDst[wid];
      xdN0 = src_h[d*128+lane];    xdN1 = src_h[d*128+lane+32];
      xdN2 = src_h[d*128+lane+64]; xdN3 = src_h[d*128+lane+96];
      twdN = src_tw[d*32+lane];    tbdN = src_tb[d*32+lane];
      xsN0 = src_h[s*128+lane];    xsN1 = src_h[s*128+lane+32];
      xsN2 = src_h[s*128+lane+64]; xsN3 = src_h[s*128+lane+96];
      twsN = src_tw[s*32+lane];    tbsN = src_tb[s*32+lane];
      ehN  = edge_h[eN*32+lane];
    }
#pragma unroll
    for (int j = 0; j < 8; ++j) {
      const int c = wid + 16*j;
      const int e = eN;
      float t = tN;
      float xd0=xdN0, xd1=xdN1, xd2=xdN2, xd3=xdN3, twd=twdN, tbd=tbdN;
      float xs0=xsN0, xs1=xsN1, xs2=xsN2, xs3=xsN3, tws=twsN, tbs=tbsN, eh=ehN;
      if (j < 7) {                      // issue next row's loads now (MLP)
        const int cN = wid + 16*(j+1);
        eN = g_perm[cbase + cN];
        if (eN >= 0) {
          tN = date[eN];
          int s = src_idx[eN], d = sDst[cN];
          xdN0 = src_h[d*128+lane];    xdN1 = src_h[d*128+lane+32];
          xdN2 = src_h[d*128+lane+64]; xdN3 = src_h[d*128+lane+96];
          twdN = src_tw[d*32+lane];    tbdN = src_tb[d*32+lane];
          xsN0 = src_h[s*128+lane];    xsN1 = src_h[s*128+lane+32];
          xsN2 = src_h[s*128+lane+64]; xsN3 = src_h[s*128+lane+96];
          twsN = src_tw[s*32+lane];    tbsN = src_tb[s*32+lane];
          ehN  = edge_h[eN*32+lane];
        }
      }
      if (e < 0) continue;   // pad row: stale SMEM is row-local, guarded later

      // dst LN (fused moments), fp16
      xd0 *= __sinf(twd*t + tbd);
      {
        float s1 = ((xd0+xd1)+(xd2+xd3));
        float s2 = fmaf(xd0,xd0, fmaf(xd1,xd1, fmaf(xd2,xd2, xd3*xd3)));
#pragma unroll
        for (int o = 16; o; o >>= 1) {
          s1 += __shfl_xor_sync(0xffffffffu, s1, o);
          s2 += __shfl_xor_sync(0xffffffffu, s2, o);
        }
        float mu = s1 * (1.f/128.f);
        float rs = rsqrtf(fmaf(-mu, mu, s2*(1.f/128.f)) + 1e-5f);
        float vout[4] = {xd0, xd1, xd2, xd3};
#pragma unroll
        for (int kk = 0; kk < 4; ++kk) {
          int i = lane + 32*kk;
          float v = (vout[kk]-mu)*rs*dg[i] + db[i];
          *(unsigned short*)(sm + OFF_AD + koff(c, i)) = hbits(v);
        }
      }
      // src LN (160 dims), fp16
      xs0 *= __sinf(tws*t + tbs);
      {
        float s1 = (((xs0+xs1)+(xs2+xs3))+eh);
        float s2 = fmaf(xs0,xs0, fmaf(xs1,xs1, fmaf(xs2,xs2, fmaf(xs3,xs3, eh*eh))));
#pragma unroll
        for (int o = 16; o; o >>= 1) {
          s1 += __shfl_xor_sync(0xffffffffu, s1, o);
          s2 += __shfl_xor_sync(0xffffffffu, s2, o);
        }
        float mu = s1 * (1.f/160.f);
        float rs = rsqrtf(fmaf(-mu, mu, s2*(1.f/160.f)) + 1e-5f);
        float vout[5] = {xs0, xs1, xs2, xs3, eh};
#pragma unroll
        for (int kk = 0; kk < 5; ++kk) {
          int i = lane + 32*kk;
          float v = (vout[kk]-mu)*rs*sg[i] + sb[i];
          *(unsigned short*)(sm + OFF_AS_HI + koff(c, i)) = hbits(v);
        }
        uint32_t o2 = koff(c, 160 + lane);   // K-pad [160,192)
        *(unsigned short*)(sm + OFF_AS_HI + o2) = 0;
      }
    }
  }
  CP_WAIT1();          // B1 (Bq) ready; B2 may still be in flight
  __syncthreads();

  const int m0 = (wid >> 2) * 32;
  const int n0 = (wid & 3) * 32;

  // ---- q GEMM: single fp16 pass ----
  float accQ[2][4][4];
#pragma unroll
  for (int a = 0; a < 2; ++a)
#pragma unroll
    for (int b = 0; b < 4; ++b)
#pragma unroll
      for (int cc = 0; cc < 4; ++cc) accQ[a][b][cc] = 0.f;
  gemm_pass<8,2>(smb + OFF_AD, smb + OFF_B1, m0, n0, lane, accQ);
  __syncthreads();     // all reads of B1 done

  // C3: Bv_hi -> B1 (overlaps k GEMM)
  { const uchar* b = g_Bv + et*49152;
    for (int o = tid*16; o < 49152; o += 8192) cp16(smb + OFF_B1 + o, b + o); }
  CP_COMMIT();
  CP_WAIT1();          // ensures C2 (Bk) done; C3 may pend
  __syncthreads();

  // ---- k GEMM: single fp16 pass, full 32-col tile ----
  float accC[2][4][4];
#pragma unroll
  for (int a = 0; a < 2; ++a)
#pragma unroll
    for (int b = 0; b < 4; ++b)
#pragma unroll
      for (int cc = 0; cc < 4; ++cc) accC[a][b][cc] = 0.f;
  gemm_pass<10,2>(smb + OFF_AS_HI, smb + OFF_B2, m0, n0, lane, accC);

  // ---- logits: per-head q.k dots; exp; fp16 ex; denominators ----
  const float scl = 0.0883883476483184f;  // 1/sqrt(128)
#pragma unroll
  for (int h = 0; h < 2; ++h) {
    const int head = (n0 >> 4) + h;
#pragma unroll
    for (int mi = 0; mi < 2; ++mi)
#pragma unroll
      for (int rh = 0; rh < 2; ++rh) {
        float p = 0.f;
#pragma unroll
        for (int nj = 0; nj < 2; ++nj) {
          p = fmaf(accQ[mi][2*h+nj][2*rh],   accC[mi][2*h+nj][2*rh],   p);
          p = fmaf(accQ[mi][2*h+nj][2*rh+1], accC[mi][2*h+nj][2*rh+1], p);
        }
        p += __shfl_xor_sync(0xffffffffu, p, 1);
        p += __shfl_xor_sync(0xffffffffu, p, 2);
        if ((lane & 3) == 0) {
          int row = m0 + mi*16 + rh*8 + (lane >> 2);
          __half exh = __float2half_rn(__expf(p * scl));
          sEx[row*8 + head] = exh;
          int d = sDst[row];
          if (d >= 0) atomicAdd(&g_denom[d*8 + head], __half2float(exh));
        }
      }
  }
  CP_WAIT0();          // Bv ready
  __syncthreads();

  // ---- v GEMM: single fp16 pass (A_s hi vs Bv_hi) ----
  float accV[2][4][4];
#pragma unroll
  for (int a = 0; a < 2; ++a)
#pragma unroll
    for (int b = 0; b < 4; ++b)
#pragma unroll
      for (int cc = 0; cc < 4; ++cc) accV[a][b][cc] = 0.f;
  gemm_pass<10,2>(smb + OFF_AS_HI, smb + OFF_B1, m0, n0, lane, accV);
  __syncthreads();     // A_d/A_s reads done -> reuse [0,64K) as bounce

  // ---- epilogue: scale by ex -> xor-swizzled bounce -> red.v4 scatter ----
  {
    float* bounce = (float*)sm;   // 64KB over A_d + AS_HI head
#pragma unroll
    for (int mi = 0; mi < 2; ++mi)
#pragma unroll
      for (int nj = 0; nj < 4; ++nj) {
        int col = n0 + nj*8 + (lane & 3)*2;
        int head = (n0 >> 4) + (nj >> 1);
        int row0 = m0 + mi*16 + (lane >> 2);
        int row1 = row0 + 8;
        float ex0 = __half2float(sEx[row0*8 + head]);
        float ex1 = __half2float(sEx[row1*8 + head]);
        *(float2*)&bounce[row0*128 + (col ^ ((row0 & 7) << 2))] =
            make_float2(accV[mi][nj][0]*ex0, accV[mi][nj][1]*ex0);
        *(float2*)&bounce[row1*128 + (col ^ ((row1 & 7) << 2))] =
            make_float2(accV[mi][nj][2]*ex1, accV[mi][nj][3]*ex1);
      }
  }
  __syncthreads();
  {
    const float* bounce = (const float*)sm;
#pragma unroll
    for (int i = 0; i < 8; ++i) {
      int e = wid*8 + i;
      int d = sDst[e];
      if (d < 0) continue;
      int col = (lane*4) ^ ((e & 7) << 2);
      float4 v = *(const float4*)&bounce[e*128 + col];
      red4(&g_num[d*128 + (lane*4)], v);
    }
  }
}

// ====== output kernel: MMA over type-pure 64-node chunks ==================
__global__ void __launch_bounds__(256) k_out(
    const float* __restrict__ src_h, const int* __restrict__ ntype,
    const float* __restrict__ h_bias, const float* __restrict__ skip,
    float* __restrict__ out)
{
  extern __shared__ __align__(1024) char sm[];
  int* sNode = (int*)(sm + O_ND);
  const uint32_t smb = (uint32_t)__cvta_generic_to_shared(sm);
  const int tid = threadIdx.x, wid = tid >> 5, lane = tid & 31;

  const int m0n = g_nperm[blockIdx.x * 64];
  if (m0n < 0) return;             // pad-only chunk
  const int tt = ntype[m0n];

  // stage Wa fp16 image (32KB) while we normalize h
  { const uchar* b = g_Ba + tt*32768;
    for (int o = tid*16; o < 32768; o += 4096) cp16(smb + O_B + o, b + o); }
  CP_COMMIT();
  if (tid < 64) sNode[tid] = g_nperm[blockIdx.x*64 + tid];
  __syncthreads();

  // ---- h = num/denom + bias -> fp16 hi/lo A-image (row = node-in-chunk) ----
  {
    const int row = tid >> 2;            // 0..63
    const int q = (tid & 3) * 32;        // col base
    const int m = sNode[row];
    float inv0 = 0.f, inv1 = 0.f;
    if (m >= 0) {
      float d0 = g_denom[m*8 + (q >> 4)];
      float d1 = g_denom[m*8 + (q >> 4) + 1];
      inv0 = (d0 > 0.f) ? 1.f/d0 : 0.f;
      inv1 = (d1 > 0.f) ? 1.f/d1 : 0.f;
    }
#pragma unroll
    for (int cc = 0; cc < 32; cc += 4) {
      int col = q + cc;
      float h0=0.f, h1=0.f, h2=0.f, h3=0.f;
      if (m >= 0) {
        float4 v = *(const float4*)&g_num[m*128 + col];
        float4 b = *(const float4*)&h_bias[tt*128 + col];
        float inv = (cc < 16) ? inv0 : inv1;
        h0 = fmaf(v.x, inv, b.x); h1 = fmaf(v.y, inv, b.y);
        h2 = fmaf(v.z, inv, b.z); h3 = fmaf(v.w, inv, b.w);
      }
      __half hh0 = __float2half_rn(h0), hh1 = __float2half_rn(h1);
      __half hh2 = __float2half_rn(h2), hh3 = __float2half_rn(h3);
      uint32_t o = koff(row, col);       // 8B-aligned, swizzle-uniform run
      *(uint2*)(sm + O_AH + o) = make_uint2(
          (uint32_t)hbits(h0) | ((uint32_t)hbits(h1) << 16),
          (uint32_t)hbits(h2) | ((uint32_t)hbits(h3) << 16));
      *(uint2*)(sm + O_AL + o) = make_uint2(
          (uint32_t)hbits(h0 - __half2float(hh0)) | ((uint32_t)hbits(h1 - __half2float(hh1)) << 16),
          (uint32_t)hbits(h2 - __half2float(hh2)) | ((uint32_t)hbits(h3 - __half2float(hh3)) << 16));
    }
  }
  CP_WAIT0();
  __syncthreads();

  // ---- GEMM 64x128x128: 2 compensated passes; warp tile 32x32 ----
  const int mw = (wid >> 2) * 32;        // 0 or 32
  const int nw = (wid & 3) * 32;
  float accO[2][4][4];
#pragma unroll
  for (int a = 0; a < 2; ++a)
#pragma unroll
    for (int b = 0; b < 4; ++b)
#pragma unroll
      for (int cc = 0; cc < 4; ++cc) accO[a][b][cc] = 0.f;
  gemm_pass<8,2>(smb + O_AH, smb + O_B, mw, nw, lane, accO);
  gemm_pass<8,2>(smb + O_AL, smb + O_B, mw, nw, lane, accO);

  // ---- epilogue: gated blend, direct coalesced STG ----
  const float gate = 1.f / (1.f + __expf(-skip[tt]));
  const float omg = 1.f - gate;
#pragma unroll
  for (int mi = 0; mi < 2; ++mi)
#pragma unroll
    for (int rh = 0; rh < 2; ++rh) {
      int row = mw + mi*16 + rh*8 + (lane >> 2);
      int mm = sNode[row];
      if (mm < 0) continue;
#pragma unroll
      for (int nj = 0; nj < 4; ++nj) {
        int col = nw + nj*8 + (lane & 3)*2;
        float2 s = *(const float2*)&src_h[mm*128 + col];
        float2 o;
        o.x = accO[mi][nj][2*rh]   * gate + s.x * omg;
        o.y = accO[mi][nj][2*rh+1] * gate + s.y * omg;
        *(float2*)&out[mm*128 + col] = o;
      }
    }
}

extern "C" void kernel_launch(void* const* d_in, const int* in_sizes, int n_in,
                              void* d_out, int out_size) {
  const float* src_h  = (const float*)d_in[0];
  const float* src_tw = (const float*)d_in[1];
  const float* src_tb = (const float*)d_in[2];
  const float* edge_h = (const float*)d_in[3];
  const float* date   = (const float*)d_in[4];
  const int*   src_idx= (const int*)d_in[5];
  const int*   dst_idx= (const int*)d_in[6];
  const int*   etype  = (const int*)d_in[7];
  const int*   ntype  = (const int*)d_in[8];
  const float* Wq     = (const float*)d_in[9];
  const float* Wk     = (const float*)d_in[10];
  const float* Wv     = (const float*)d_in[11];
  const float* Wa     = (const float*)d_in[12];
  const float* h_bias = (const float*)d_in[13];
  const float* skip   = (const float*)d_in[14];
  const float* sg     = (const float*)d_in[15];
  const float* sb     = (const float*)d_in[16];
  const float* dg     = (const float*)d_in[17];
  const float* db     = (const float*)d_in[18];
  float* out = (float*)d_out;

  const int E = in_sizes[4];
  const int M = in_sizes[8];
  const int NB = (E + CSZ - 1)/CSZ + RTYPES;
  const int NNB = (M + 63)/64 + TTYPES;
  const int EB = (E + 1023)/1024;
  const int MB = (M + 1023)/1024;

  cudaFuncSetAttribute(k_edge, cudaFuncAttributeMaxDynamicSharedMemorySize, SMEM_EDGE);
  cudaFuncSetAttribute(k_out, cudaFuncAttributeMaxDynamicSharedMemorySize, SMEM_OUT);

  const int initTasks = M*32 + M*2 + PCAP/4 + NPCAP/4;
  const int NBI = (initTasks + 255) / 256;
  const int NBP = (32768 + 2*49152 + 16384 + 255) / 256;   // 576
  k_prep<<<NBI + 144 + NBP, 256>>>(etype, ntype, E, M, Wq, Wk, Wv, Wa, NBI);
  k_scatter<<<EB + MB, 256>>>(etype, E, ntype, M, EB);
  k_edge<<<NB, 512, SMEM_EDGE>>>(src_h, src_tw, src_tb, edge_h, date,
                                 src_idx, dst_idx, etype, sg, sb, dg, db);
  k_out<<<NNB, 256, SMEM_OUT>>>(src_h, ntype, h_bias, skip, out);
}